// round 1
// baseline (speedup 1.0000x reference)
#include <cuda_runtime.h>
#include <cuda_bf16.h>
#include <math.h>

#define BATCH 2
#define SEQ 2048
#define NH 16
#define HD 128
#define DM 2048
#define MROWS (BATCH*SEQ)     // 4096
#define NQKV (3*DM)           // 6144
#define SCALE 0.08838834764831845f  // 1/sqrt(128)

// ---------------- scratch (static device globals: allocation-free) ----------
__device__ float g_Q[BATCH*NH*SEQ*HD];   // [b,h,s,d]
__device__ float g_K[BATCH*NH*SEQ*HD];
__device__ float g_V[BATCH*NH*SEQ*HD];
__device__ float g_ctx[MROWS*DM];        // [b*s, h*d]
__device__ float g_cos[SEQ*64];
__device__ float g_sin[SEQ*64];

// ---------------- RoPE table (double precision, tiny) ----------------------
__global__ void build_rope_kernel() {
    int idx = blockIdx.x * blockDim.x + threadIdx.x;
    if (idx >= SEQ * 64) return;
    int pos = idx >> 6, i = idx & 63;
    double f = pow(10000.0, -(double)i / 64.0);
    double a = (double)pos * f;
    g_cos[idx] = (float)cos(a);
    g_sin[idx] = (float)sin(a);
}

// ---------------- shared 128x128x16 NT SGEMM mainloop -----------------------
// C[128,128] tile of A[M,K] @ B[N,K]^T. Ag/Bg pre-offset to tile row 0.
// 256 threads, 8x8 per thread with 4+4 split, register prefetch of next tile.
__device__ __forceinline__ void gemm_mainloop(
    const float* __restrict__ Ag, const float* __restrict__ Bg,
    int K, float (&acc)[8][8])
{
    __shared__ float As[16][132];
    __shared__ float Bs[16][132];

    const int tid = threadIdx.x;
    const int tx = tid & 15, ty = tid >> 4;
    const int r0  = tid >> 2;          // 0..63
    const int kc0 = (tid & 3) * 4;     // 0,4,8,12
    const int KT = K >> 4;

    float4 pa0, pa1, pb0, pb1;

    // prologue: tile 0
    pa0 = *(const float4*)(Ag + (size_t)r0 * K + kc0);
    pa1 = *(const float4*)(Ag + (size_t)(r0 + 64) * K + kc0);
    pb0 = *(const float4*)(Bg + (size_t)r0 * K + kc0);
    pb1 = *(const float4*)(Bg + (size_t)(r0 + 64) * K + kc0);
    As[kc0+0][r0] = pa0.x; As[kc0+1][r0] = pa0.y; As[kc0+2][r0] = pa0.z; As[kc0+3][r0] = pa0.w;
    As[kc0+0][r0+64] = pa1.x; As[kc0+1][r0+64] = pa1.y; As[kc0+2][r0+64] = pa1.z; As[kc0+3][r0+64] = pa1.w;
    Bs[kc0+0][r0] = pb0.x; Bs[kc0+1][r0] = pb0.y; Bs[kc0+2][r0] = pb0.z; Bs[kc0+3][r0] = pb0.w;
    Bs[kc0+0][r0+64] = pb1.x; Bs[kc0+1][r0+64] = pb1.y; Bs[kc0+2][r0+64] = pb1.z; Bs[kc0+3][r0+64] = pb1.w;
    __syncthreads();

    for (int kb = 0; kb < KT; kb++) {
        bool has_next = (kb + 1 < KT);
        if (has_next) {
            int ko = (kb + 1) * 16 + kc0;
            pa0 = *(const float4*)(Ag + (size_t)r0 * K + ko);
            pa1 = *(const float4*)(Ag + (size_t)(r0 + 64) * K + ko);
            pb0 = *(const float4*)(Bg + (size_t)r0 * K + ko);
            pb1 = *(const float4*)(Bg + (size_t)(r0 + 64) * K + ko);
        }
        #pragma unroll
        for (int k = 0; k < 16; k++) {
            float a[8], b[8];
            *(float4*)&a[0] = *(const float4*)&As[k][ty * 4];
            *(float4*)&a[4] = *(const float4*)&As[k][64 + ty * 4];
            *(float4*)&b[0] = *(const float4*)&Bs[k][tx * 4];
            *(float4*)&b[4] = *(const float4*)&Bs[k][64 + tx * 4];
            #pragma unroll
            for (int i = 0; i < 8; i++)
                #pragma unroll
                for (int j = 0; j < 8; j++)
                    acc[i][j] += a[i] * b[j];
        }
        __syncthreads();
        if (has_next) {
            As[kc0+0][r0] = pa0.x; As[kc0+1][r0] = pa0.y; As[kc0+2][r0] = pa0.z; As[kc0+3][r0] = pa0.w;
            As[kc0+0][r0+64] = pa1.x; As[kc0+1][r0+64] = pa1.y; As[kc0+2][r0+64] = pa1.z; As[kc0+3][r0+64] = pa1.w;
            Bs[kc0+0][r0] = pb0.x; Bs[kc0+1][r0] = pb0.y; Bs[kc0+2][r0] = pb0.z; Bs[kc0+3][r0] = pb0.w;
            Bs[kc0+0][r0+64] = pb1.x; Bs[kc0+1][r0+64] = pb1.y; Bs[kc0+2][r0+64] = pb1.z; Bs[kc0+3][r0+64] = pb1.w;
            __syncthreads();
        }
    }
}

// ---------------- QKV GEMM with fused bias + RoPE + scatter -----------------
__global__ void __launch_bounds__(256) qkv_gemm_kernel(
    const float* __restrict__ X, const float* __restrict__ W,
    const float* __restrict__ bias)
{
    float acc[8][8];
    #pragma unroll
    for (int i = 0; i < 8; i++)
        #pragma unroll
        for (int j = 0; j < 8; j++) acc[i][j] = 0.f;

    const int m0 = blockIdx.y * 128;
    const int n0 = blockIdx.x * 128;
    gemm_mainloop(X + (size_t)m0 * DM, W + (size_t)n0 * DM, DM, acc);

    const int tid = threadIdx.x;
    const int tx = tid & 15, ty = tid >> 4;
    const int comp = n0 >> 11;            // 0=Q, 1=K, 2=V
    const int h = (n0 >> 7) & 15;
    float* dstQK = (comp == 0) ? g_Q : g_K;

    #pragma unroll
    for (int i = 0; i < 8; i++) {
        int rloc = (i < 4) ? (ty * 4 + i) : (64 + ty * 4 + (i - 4));
        int m = m0 + rloc;
        int b = m >> 11, s = m & 2047;
        size_t base = ((size_t)(b * NH + h) * SEQ + s) * HD;
        #pragma unroll
        for (int jj = 0; jj < 4; jj++) {
            int d0 = tx * 4 + jj, d1 = d0 + 64;
            float v0 = acc[i][jj]     + bias[n0 + d0];
            float v1 = acc[i][jj + 4] + bias[n0 + d1];
            if (comp == 2) {
                g_V[base + d0] = v0;
                g_V[base + d1] = v1;
            } else {
                float c  = g_cos[s * 64 + d0];
                float sn = g_sin[s * 64 + d0];
                dstQK[base + d0] = v0 * c - v1 * sn;
                dstQK[base + d1] = v1 * c + v0 * sn;
            }
        }
    }
}

// ---------------- output projection GEMM (reads g_ctx) ----------------------
__global__ void __launch_bounds__(256) out_gemm_kernel(
    const float* __restrict__ W, const float* __restrict__ bias,
    float* __restrict__ C)
{
    float acc[8][8];
    #pragma unroll
    for (int i = 0; i < 8; i++)
        #pragma unroll
        for (int j = 0; j < 8; j++) acc[i][j] = 0.f;

    const int m0 = blockIdx.y * 128;
    const int n0 = blockIdx.x * 128;
    gemm_mainloop(g_ctx + (size_t)m0 * DM, W + (size_t)n0 * DM, DM, acc);

    const int tid = threadIdx.x;
    const int tx = tid & 15, ty = tid >> 4;
    #pragma unroll
    for (int i = 0; i < 8; i++) {
        int rloc = (i < 4) ? (ty * 4 + i) : (64 + ty * 4 + (i - 4));
        size_t row = (size_t)(m0 + rloc) * DM;
        #pragma unroll
        for (int j = 0; j < 8; j++) {
            int cloc = (j < 4) ? (tx * 4 + j) : (64 + tx * 4 + (j - 4));
            C[row + n0 + cloc] = acc[i][j] + bias[n0 + cloc];
        }
    }
}

// ---------------- flash-style causal attention ------------------------------
// Block = (64 query rows) x (one b,h). Smem: Qt[128][68], Kt[128][68],
// V[64][128], P[64][68]. 256 threads: S tile 4x4 each, O tile 4x8 each.
__global__ void __launch_bounds__(256) attn_kernel() {
    extern __shared__ float sm[];
    float* Qts = sm;                    // [128][68] transposed
    float* Kts = Qts + 128 * 68;        // [128][68] transposed
    float* Vs  = Kts + 128 * 68;        // [64][128]
    float* Ps  = Vs + 64 * 128;         // [64][68]

    const int tid = threadIdx.x;
    const int tx = tid & 15, ty = tid >> 4;
    const int qb = blockIdx.x;
    const int bh = blockIdx.y;

    const float* Qg  = g_Q + (size_t)bh * SEQ * HD + (size_t)qb * 64 * HD;
    const float* Kg0 = g_K + (size_t)bh * SEQ * HD;
    const float* Vg0 = g_V + (size_t)bh * SEQ * HD;

    // load Q tile transposed
    #pragma unroll
    for (int it = 0; it < 8; it++) {
        int f = tid + it * 256;
        int r = f >> 5;
        int c4 = (f & 31) * 4;
        float4 v = *(const float4*)(Qg + r * HD + c4);
        Qts[(c4 + 0) * 68 + r] = v.x;
        Qts[(c4 + 1) * 68 + r] = v.y;
        Qts[(c4 + 2) * 68 + r] = v.z;
        Qts[(c4 + 3) * 68 + r] = v.w;
    }

    float o[4][8];
    float mrow[4], lrow[4];
    #pragma unroll
    for (int i = 0; i < 4; i++) {
        mrow[i] = -1e30f; lrow[i] = 0.f;
        #pragma unroll
        for (int j = 0; j < 8; j++) o[i][j] = 0.f;
    }

    for (int kb = 0; kb <= qb; kb++) {
        __syncthreads();  // protect Kts/Vs/Ps reuse (and initial Q load)
        const float* Kg = Kg0 + (size_t)kb * 64 * HD;
        const float* Vg = Vg0 + (size_t)kb * 64 * HD;
        #pragma unroll
        for (int it = 0; it < 8; it++) {
            int f = tid + it * 256;
            int r = f >> 5;
            int c4 = (f & 31) * 4;
            float4 kv = *(const float4*)(Kg + r * HD + c4);
            Kts[(c4 + 0) * 68 + r] = kv.x;
            Kts[(c4 + 1) * 68 + r] = kv.y;
            Kts[(c4 + 2) * 68 + r] = kv.z;
            Kts[(c4 + 3) * 68 + r] = kv.w;
            float4 vv = *(const float4*)(Vg + r * HD + c4);
            *(float4*)(Vs + r * 128 + c4) = vv;
        }
        __syncthreads();

        // S = Q @ K^T  (4x4 per thread)
        float sacc[4][4];
        #pragma unroll
        for (int i = 0; i < 4; i++)
            #pragma unroll
            for (int j = 0; j < 4; j++) sacc[i][j] = 0.f;

        #pragma unroll 4
        for (int k = 0; k < 128; k++) {
            float q[4], kk[4];
            *(float4*)&q[0]  = *(const float4*)(Qts + k * 68 + ty * 4);
            *(float4*)&kk[0] = *(const float4*)(Kts + k * 68 + tx * 4);
            #pragma unroll
            for (int i = 0; i < 4; i++)
                #pragma unroll
                for (int j = 0; j < 4; j++)
                    sacc[i][j] += q[i] * kk[j];
        }

        const int rowg0 = qb * 64 + ty * 4;
        const int colg0 = kb * 64 + tx * 4;
        #pragma unroll
        for (int i = 0; i < 4; i++) {
            #pragma unroll
            for (int j = 0; j < 4; j++) {
                sacc[i][j] *= SCALE;
                if (colg0 + j > rowg0 + i) sacc[i][j] = -1e30f;
            }
            // row max across the 16 tx lanes
            float rmax = fmaxf(fmaxf(sacc[i][0], sacc[i][1]),
                               fmaxf(sacc[i][2], sacc[i][3]));
            #pragma unroll
            for (int mm = 8; mm >= 1; mm >>= 1)
                rmax = fmaxf(rmax, __shfl_xor_sync(0xffffffffu, rmax, mm));
            float mn = fmaxf(mrow[i], rmax);
            float alpha = __expf(mrow[i] - mn);
            mrow[i] = mn;
            float rsum = 0.f;
            #pragma unroll
            for (int j = 0; j < 4; j++) {
                float p = __expf(sacc[i][j] - mn);
                sacc[i][j] = p;
                rsum += p;
            }
            #pragma unroll
            for (int mm = 8; mm >= 1; mm >>= 1)
                rsum += __shfl_xor_sync(0xffffffffu, rsum, mm);
            lrow[i] = lrow[i] * alpha + rsum;
            #pragma unroll
            for (int j = 0; j < 8; j++) o[i][j] *= alpha;
            #pragma unroll
            for (int j = 0; j < 4; j++)
                Ps[(ty * 4 + i) * 68 + tx * 4 + j] = sacc[i][j];
        }
        __syncthreads();

        // O += P @ V
        #pragma unroll 4
        for (int kk2 = 0; kk2 < 64; kk2++) {
            float4 v0 = *(const float4*)(Vs + kk2 * 128 + tx * 4);
            float4 v1 = *(const float4*)(Vs + kk2 * 128 + 64 + tx * 4);
            #pragma unroll
            for (int i = 0; i < 4; i++) {
                float p = Ps[(ty * 4 + i) * 68 + kk2];
                o[i][0] += p * v0.x; o[i][1] += p * v0.y;
                o[i][2] += p * v0.z; o[i][3] += p * v0.w;
                o[i][4] += p * v1.x; o[i][5] += p * v1.y;
                o[i][6] += p * v1.z; o[i][7] += p * v1.w;
            }
        }
    }

    // write ctx in [b*s, h*128+d] layout for the output GEMM
    const int b = bh >> 4, h = bh & 15;
    #pragma unroll
    for (int i = 0; i < 4; i++) {
        float inv = 1.0f / lrow[i];
        int s = qb * 64 + ty * 4 + i;
        size_t rowbase = ((size_t)b * SEQ + s) * DM + h * HD;
        #pragma unroll
        for (int j = 0; j < 4; j++)
            g_ctx[rowbase + tx * 4 + j] = o[i][j] * inv;
        #pragma unroll
        for (int j = 0; j < 4; j++)
            g_ctx[rowbase + 64 + tx * 4 + j] = o[i][j + 4] * inv;
    }
}

// ---------------- launch ----------------------------------------------------
extern "C" void kernel_launch(void* const* d_in, const int* in_sizes, int n_in,
                              void* d_out, int out_size) {
    const float* x      = (const float*)d_in[0];
    // d_in[1] = attn_mask (causal, recomputed on the fly; unused)
    const float* Wqkv_w = (const float*)d_in[2];
    const float* Wqkv_b = (const float*)d_in[3];
    const float* out_w  = (const float*)d_in[4];
    const float* out_b  = (const float*)d_in[5];
    float* out = (float*)d_out;

    build_rope_kernel<<<(SEQ * 64 + 255) / 256, 256>>>();
    qkv_gemm_kernel<<<dim3(NQKV / 128, MROWS / 128), 256>>>(x, Wqkv_w, Wqkv_b);

    const int ATTN_SMEM = (128 * 68 * 2 + 64 * 128 + 64 * 68) * 4;  // 119808 B
    cudaFuncSetAttribute(attn_kernel,
                         cudaFuncAttributeMaxDynamicSharedMemorySize, ATTN_SMEM);
    attn_kernel<<<dim3(SEQ / 64, BATCH * NH), 256, ATTN_SMEM>>>();

    out_gemm_kernel<<<dim3(DM / 128, MROWS / 128), 256>>>(out_w, out_b, out);
}

// round 3
// speedup vs baseline: 1.4381x; 1.4381x over previous
#include <cuda_runtime.h>
#include <cuda_bf16.h>
#include <cstdint>
#include <stdint.h>
#include <math.h>

#define BATCH 2
#define SEQ 2048
#define NH 16
#define HD 128
#define DM 2048
#define MROWS (BATCH*SEQ)     // 4096
#define NQKV (3*DM)           // 6144
#define SCALE 0.08838834764831845f  // 1/sqrt(128)

// ---------------- scratch (static device globals: allocation-free) ----------
__device__ float g_Q[BATCH*NH*SEQ*HD];   // [b,h,s,d]
__device__ float g_K[BATCH*NH*SEQ*HD];
__device__ float g_V[BATCH*NH*SEQ*HD];
__device__ float g_ctx[MROWS*DM];        // [b*s, h*d]
__device__ float g_cos[SEQ*64];
__device__ float g_sin[SEQ*64];

// ---------------- RoPE table -------------------------------------------------
__global__ void build_rope_kernel() {
    int idx = blockIdx.x * blockDim.x + threadIdx.x;
    if (idx >= SEQ * 64) return;
    int pos = idx >> 6, i = idx & 63;
    double f = pow(10000.0, -(double)i / 64.0);
    double a = (double)pos * f;
    g_cos[idx] = (float)cos(a);
    g_sin[idx] = (float)sin(a);
}

// ---------------- tf32 helpers ----------------------------------------------
__device__ __forceinline__ float cvt_tf32(float x) {
    unsigned int r;
    asm("cvt.rna.tf32.f32 %0, %1;" : "=r"(r) : "f"(x));
    return __uint_as_float(r);
}

__device__ __forceinline__ void mma_tf32(float (&cacc)[4],
                                         const unsigned int (&a)[4],
                                         const unsigned int (&b)[2]) {
    asm volatile(
        "mma.sync.aligned.m16n8k8.row.col.f32.tf32.tf32.f32 "
        "{%0,%1,%2,%3}, {%4,%5,%6,%7}, {%8,%9}, {%0,%1,%2,%3};\n"
        : "+f"(cacc[0]), "+f"(cacc[1]), "+f"(cacc[2]), "+f"(cacc[3])
        : "r"(a[0]), "r"(a[1]), "r"(a[2]), "r"(a[3]), "r"(b[0]), "r"(b[1]));
}

// ---------------- tf32 tensor-core 128x128xK NT GEMM mainloop ---------------
// C tile = A[128 rows of M] @ B[128 rows of N]^T. Ag/Bg pre-offset.
// 256 threads = 8 warps (2m x 4n). Warp tile 64x32 via m16n8k8.
// Warp n-subtiles at {nw*16, nw*16+8, 64+nw*16, 64+nw*16+8} so each thread
// owns both halves of every rotate-half pair (d, d+64).
// acc[mt][nt][4] with nt pairs (0,2) and (1,3) = (d, d+64).
__device__ __forceinline__ void gemm_tf32_mainloop(
    const float* __restrict__ Ag, const float* __restrict__ Bg,
    int K, float (&acc)[4][4][4])
{
    __shared__ float As[2][16][136];   // [buf][k][m], pad 136 -> conflict-free frag reads
    __shared__ float Bs[2][16][136];   // [buf][k][n]

    const int tid = threadIdx.x;
    const int lane = tid & 31;
    const int wid = tid >> 5;
    const int g = lane >> 2;           // groupID 0..7
    const int c = lane & 3;            // threadID_in_group 0..3
    const int r0 = tid >> 2;           // 0..63
    const int kc0 = (tid & 3) * 4;     // 0,4,8,12
    const int mwarp = wid >> 2;        // 0..1
    const int nwarp = wid & 3;         // 0..3
    const int KT = K >> 4;

    float4 pa0, pa1, pb0, pb1;

    pa0 = *(const float4*)(Ag + (size_t)r0 * K + kc0);
    pa1 = *(const float4*)(Ag + (size_t)(r0 + 64) * K + kc0);
    pb0 = *(const float4*)(Bg + (size_t)r0 * K + kc0);
    pb1 = *(const float4*)(Bg + (size_t)(r0 + 64) * K + kc0);
    {
        float a0[4] = {pa0.x, pa0.y, pa0.z, pa0.w};
        float a1[4] = {pa1.x, pa1.y, pa1.z, pa1.w};
        float b0[4] = {pb0.x, pb0.y, pb0.z, pb0.w};
        float b1[4] = {pb1.x, pb1.y, pb1.z, pb1.w};
        #pragma unroll
        for (int j = 0; j < 4; j++) {
            As[0][kc0 + j][r0]      = cvt_tf32(a0[j]);
            As[0][kc0 + j][r0 + 64] = cvt_tf32(a1[j]);
            Bs[0][kc0 + j][r0]      = cvt_tf32(b0[j]);
            Bs[0][kc0 + j][r0 + 64] = cvt_tf32(b1[j]);
        }
    }
    __syncthreads();

    for (int kb = 0; kb < KT; kb++) {
        const int buf = kb & 1;
        const bool has_next = (kb + 1 < KT);
        if (has_next) {
            int ko = (kb + 1) * 16 + kc0;
            pa0 = *(const float4*)(Ag + (size_t)r0 * K + ko);
            pa1 = *(const float4*)(Ag + (size_t)(r0 + 64) * K + ko);
            pb0 = *(const float4*)(Bg + (size_t)r0 * K + ko);
            pb1 = *(const float4*)(Bg + (size_t)(r0 + 64) * K + ko);
        }

        #pragma unroll
        for (int ks = 0; ks < 2; ks++) {
            const int kk = ks * 8;
            unsigned int af[4][4];
            unsigned int bf[4][2];
            #pragma unroll
            for (int mt = 0; mt < 4; mt++) {
                int m = mwarp * 64 + mt * 16 + g;
                af[mt][0] = __float_as_uint(As[buf][kk + c][m]);
                af[mt][1] = __float_as_uint(As[buf][kk + c][m + 8]);
                af[mt][2] = __float_as_uint(As[buf][kk + c + 4][m]);
                af[mt][3] = __float_as_uint(As[buf][kk + c + 4][m + 8]);
            }
            #pragma unroll
            for (int nt = 0; nt < 4; nt++) {
                int n = nwarp * 16 + (nt & 1) * 8 + (nt >> 1) * 64 + g;
                bf[nt][0] = __float_as_uint(Bs[buf][kk + c][n]);
                bf[nt][1] = __float_as_uint(Bs[buf][kk + c + 4][n]);
            }
            #pragma unroll
            for (int mt = 0; mt < 4; mt++)
                #pragma unroll
                for (int nt = 0; nt < 4; nt++)
                    mma_tf32(acc[mt][nt], af[mt], bf[nt]);
        }

        if (has_next) {
            const int nb = buf ^ 1;
            float a0[4] = {pa0.x, pa0.y, pa0.z, pa0.w};
            float a1[4] = {pa1.x, pa1.y, pa1.z, pa1.w};
            float b0[4] = {pb0.x, pb0.y, pb0.z, pb0.w};
            float b1[4] = {pb1.x, pb1.y, pb1.z, pb1.w};
            #pragma unroll
            for (int j = 0; j < 4; j++) {
                As[nb][kc0 + j][r0]      = cvt_tf32(a0[j]);
                As[nb][kc0 + j][r0 + 64] = cvt_tf32(a1[j]);
                Bs[nb][kc0 + j][r0]      = cvt_tf32(b0[j]);
                Bs[nb][kc0 + j][r0 + 64] = cvt_tf32(b1[j]);
            }
            __syncthreads();
        }
    }
}

// ---------------- QKV GEMM with fused bias + RoPE + scatter -----------------
__global__ void __launch_bounds__(256) qkv_gemm_kernel(
    const float* __restrict__ X, const float* __restrict__ W,
    const float* __restrict__ bias)
{
    float acc[4][4][4];
    #pragma unroll
    for (int i = 0; i < 4; i++)
        #pragma unroll
        for (int j = 0; j < 4; j++)
            #pragma unroll
            for (int k = 0; k < 4; k++) acc[i][j][k] = 0.f;

    const int m0 = blockIdx.y * 128;
    const int n0 = blockIdx.x * 128;
    gemm_tf32_mainloop(X + (size_t)m0 * DM, W + (size_t)n0 * DM, DM, acc);

    const int tid = threadIdx.x;
    const int lane = tid & 31;
    const int wid = tid >> 5;
    const int g = lane >> 2, c = lane & 3;
    const int mwarp = wid >> 2, nwarp = wid & 3;

    const int comp = n0 >> 11;            // 0=Q, 1=K, 2=V
    const int h = (n0 >> 7) & 15;
    float* dstQK = (comp == 0) ? g_Q : g_K;

    #pragma unroll
    for (int mt = 0; mt < 4; mt++) {
        #pragma unroll
        for (int rr = 0; rr < 2; rr++) {
            int m = m0 + mwarp * 64 + mt * 16 + g + rr * 8;
            int b = m >> 11, s = m & 2047;
            size_t base = ((size_t)(b * NH + h) * SEQ + s) * HD;
            #pragma unroll
            for (int ntp = 0; ntp < 2; ntp++) {
                #pragma unroll
                for (int e = 0; e < 2; e++) {
                    int d0 = nwarp * 16 + ntp * 8 + c * 2 + e;   // 0..63
                    float v0 = acc[mt][ntp][rr * 2 + e]     + bias[n0 + d0];
                    float v1 = acc[mt][ntp + 2][rr * 2 + e] + bias[n0 + 64 + d0];
                    if (comp == 2) {
                        g_V[base + d0]      = v0;
                        g_V[base + 64 + d0] = v1;
                    } else {
                        float co = g_cos[s * 64 + d0];
                        float sn = g_sin[s * 64 + d0];
                        dstQK[base + d0]      = v0 * co - v1 * sn;
                        dstQK[base + 64 + d0] = v1 * co + v0 * sn;
                    }
                }
            }
        }
    }
}

// ---------------- output projection GEMM (reads g_ctx) ----------------------
__global__ void __launch_bounds__(256) out_gemm_kernel(
    const float* __restrict__ W, const float* __restrict__ bias,
    float* __restrict__ C)
{
    float acc[4][4][4];
    #pragma unroll
    for (int i = 0; i < 4; i++)
        #pragma unroll
        for (int j = 0; j < 4; j++)
            #pragma unroll
            for (int k = 0; k < 4; k++) acc[i][j][k] = 0.f;

    const int m0 = blockIdx.y * 128;
    const int n0 = blockIdx.x * 128;
    gemm_tf32_mainloop(g_ctx + (size_t)m0 * DM, W + (size_t)n0 * DM, DM, acc);

    const int tid = threadIdx.x;
    const int lane = tid & 31;
    const int wid = tid >> 5;
    const int g = lane >> 2, c = lane & 3;
    const int mwarp = wid >> 2, nwarp = wid & 3;

    #pragma unroll
    for (int mt = 0; mt < 4; mt++) {
        #pragma unroll
        for (int rr = 0; rr < 2; rr++) {
            int row = m0 + mwarp * 64 + mt * 16 + g + rr * 8;
            #pragma unroll
            for (int nt = 0; nt < 4; nt++) {
                int colb = n0 + nwarp * 16 + (nt & 1) * 8 + (nt >> 1) * 64 + c * 2;
                float2 st;
                st.x = acc[mt][nt][rr * 2]     + bias[colb];
                st.y = acc[mt][nt][rr * 2 + 1] + bias[colb + 1];
                *(float2*)(C + (size_t)row * DM + colb) = st;
            }
        }
    }
}

// ---------------- flash-style causal attention (fp32, as round 1) -----------
__global__ void __launch_bounds__(256) attn_kernel() {
    extern __shared__ float sm[];
    float* Qts = sm;                    // [128][68] transposed
    float* Kts = Qts + 128 * 68;        // [128][68] transposed
    float* Vs  = Kts + 128 * 68;        // [64][128]
    float* Ps  = Vs + 64 * 128;         // [64][68]

    const int tid = threadIdx.x;
    const int tx = tid & 15, ty = tid >> 4;
    const int qb = blockIdx.x;
    const int bh = blockIdx.y;

    const float* Qg  = g_Q + (size_t)bh * SEQ * HD + (size_t)qb * 64 * HD;
    const float* Kg0 = g_K + (size_t)bh * SEQ * HD;
    const float* Vg0 = g_V + (size_t)bh * SEQ * HD;

    #pragma unroll
    for (int it = 0; it < 8; it++) {
        int f = tid + it * 256;
        int r = f >> 5;
        int c4 = (f & 31) * 4;
        float4 v = *(const float4*)(Qg + r * HD + c4);
        Qts[(c4 + 0) * 68 + r] = v.x;
        Qts[(c4 + 1) * 68 + r] = v.y;
        Qts[(c4 + 2) * 68 + r] = v.z;
        Qts[(c4 + 3) * 68 + r] = v.w;
    }

    float o[4][8];
    float mrow[4], lrow[4];
    #pragma unroll
    for (int i = 0; i < 4; i++) {
        mrow[i] = -1e30f; lrow[i] = 0.f;
        #pragma unroll
        for (int j = 0; j < 8; j++) o[i][j] = 0.f;
    }

    for (int kb = 0; kb <= qb; kb++) {
        __syncthreads();
        const float* Kg = Kg0 + (size_t)kb * 64 * HD;
        const float* Vg = Vg0 + (size_t)kb * 64 * HD;
        #pragma unroll
        for (int it = 0; it < 8; it++) {
            int f = tid + it * 256;
            int r = f >> 5;
            int c4 = (f & 31) * 4;
            float4 kv = *(const float4*)(Kg + r * HD + c4);
            Kts[(c4 + 0) * 68 + r] = kv.x;
            Kts[(c4 + 1) * 68 + r] = kv.y;
            Kts[(c4 + 2) * 68 + r] = kv.z;
            Kts[(c4 + 3) * 68 + r] = kv.w;
            float4 vv = *(const float4*)(Vg + r * HD + c4);
            *(float4*)(Vs + r * 128 + c4) = vv;
        }
        __syncthreads();

        float sacc[4][4];
        #pragma unroll
        for (int i = 0; i < 4; i++)
            #pragma unroll
            for (int j = 0; j < 4; j++) sacc[i][j] = 0.f;

        #pragma unroll 4
        for (int k = 0; k < 128; k++) {
            float q[4], kk[4];
            *(float4*)&q[0]  = *(const float4*)(Qts + k * 68 + ty * 4);
            *(float4*)&kk[0] = *(const float4*)(Kts + k * 68 + tx * 4);
            #pragma unroll
            for (int i = 0; i < 4; i++)
                #pragma unroll
                for (int j = 0; j < 4; j++)
                    sacc[i][j] += q[i] * kk[j];
        }

        const int rowg0 = qb * 64 + ty * 4;
        const int colg0 = kb * 64 + tx * 4;
        #pragma unroll
        for (int i = 0; i < 4; i++) {
            #pragma unroll
            for (int j = 0; j < 4; j++) {
                sacc[i][j] *= SCALE;
                if (colg0 + j > rowg0 + i) sacc[i][j] = -1e30f;
            }
            float rmax = fmaxf(fmaxf(sacc[i][0], sacc[i][1]),
                               fmaxf(sacc[i][2], sacc[i][3]));
            #pragma unroll
            for (int off = 8; off >= 1; off >>= 1)
                rmax = fmaxf(rmax, __shfl_xor_sync(0xffffffffu, rmax, off));
            float mnew = fmaxf(mrow[i], rmax);
            float corr = __expf(mrow[i] - mnew);
            mrow[i] = mnew;
            float rsum = 0.f;
            #pragma unroll
            for (int j = 0; j < 4; j++) {
                float p = __expf(sacc[i][j] - mnew);
                sacc[i][j] = p;
                rsum += p;
            }
            #pragma unroll
            for (int off = 8; off >= 1; off >>= 1)
                rsum += __shfl_xor_sync(0xffffffffu, rsum, off);
            lrow[i] = lrow[i] * corr + rsum;
            #pragma unroll
            for (int j = 0; j < 8; j++) o[i][j] *= corr;
            #pragma unroll
            for (int j = 0; j < 4; j++)
                Ps[(ty * 4 + i) * 68 + tx * 4 + j] = sacc[i][j];
        }
        __syncthreads();

        #pragma unroll 4
        for (int kk2 = 0; kk2 < 64; kk2++) {
            float4 v0 = *(const float4*)(Vs + kk2 * 128 + tx * 4);
            float4 v1 = *(const float4*)(Vs + kk2 * 128 + 64 + tx * 4);
            #pragma unroll
            for (int i = 0; i < 4; i++) {
                float p = Ps[(ty * 4 + i) * 68 + kk2];
                o[i][0] += p * v0.x; o[i][1] += p * v0.y;
                o[i][2] += p * v0.z; o[i][3] += p * v0.w;
                o[i][4] += p * v1.x; o[i][5] += p * v1.y;
                o[i][6] += p * v1.z; o[i][7] += p * v1.w;
            }
        }
    }

    const int b = bh >> 4, h = bh & 15;
    #pragma unroll
    for (int i = 0; i < 4; i++) {
        float inv = 1.0f / lrow[i];
        int s = qb * 64 + ty * 4 + i;
        size_t rowbase = ((size_t)b * SEQ + s) * DM + h * HD;
        #pragma unroll
        for (int j = 0; j < 4; j++)
            g_ctx[rowbase + tx * 4 + j] = o[i][j] * inv;
        #pragma unroll
        for (int j = 0; j < 4; j++)
            g_ctx[rowbase + 64 + tx * 4 + j] = o[i][j + 4] * inv;
    }
}

// ---------------- launch ----------------------------------------------------
extern "C" void kernel_launch(void* const* d_in, const int* in_sizes, int n_in,
                              void* d_out, int out_size) {
    const float* x      = (const float*)d_in[0];
    // d_in[1] = attn_mask (causal, recomputed on the fly; unused)
    const float* Wqkv_w = (const float*)d_in[2];
    const float* Wqkv_b = (const float*)d_in[3];
    const float* out_w  = (const float*)d_in[4];
    const float* out_b  = (const float*)d_in[5];
    float* out = (float*)d_out;

    build_rope_kernel<<<(SEQ * 64 + 255) / 256, 256>>>();
    qkv_gemm_kernel<<<dim3(NQKV / 128, MROWS / 128), 256>>>(x, Wqkv_w, Wqkv_b);

    const int ATTN_SMEM = (128 * 68 * 2 + 64 * 128 + 64 * 68) * 4;  // 119808 B
    cudaFuncSetAttribute(attn_kernel,
                         cudaFuncAttributeMaxDynamicSharedMemorySize, ATTN_SMEM);
    attn_kernel<<<dim3(SEQ / 64, BATCH * NH), 256, ATTN_SMEM>>>();

    out_gemm_kernel<<<dim3(DM / 128, MROWS / 128), 256>>>(out_w, out_b, out);
}

// round 4
// speedup vs baseline: 1.9307x; 1.3425x over previous
#include <cuda_runtime.h>
#include <cuda_bf16.h>
#include <cstdint>
#include <stdint.h>
#include <math.h>

#define BATCH 2
#define SEQ 2048
#define NH 16
#define HD 128
#define DM 2048
#define MROWS (BATCH*SEQ)     // 4096
#define NQKV (3*DM)           // 6144
#define SCALE 0.08838834764831845f  // 1/sqrt(128)

// ---------------- scratch (static device globals: allocation-free) ----------
__device__ float g_Q[BATCH*NH*SEQ*HD];   // [b,h,s,d]
__device__ float g_K[BATCH*NH*SEQ*HD];
__device__ float g_V[BATCH*NH*SEQ*HD];
__device__ float g_ctx[MROWS*DM];        // [b*s, h*d]
__device__ float g_cos[SEQ*64];
__device__ float g_sin[SEQ*64];

// ---------------- RoPE table -------------------------------------------------
__global__ void build_rope_kernel() {
    int idx = blockIdx.x * blockDim.x + threadIdx.x;
    if (idx >= SEQ * 64) return;
    int pos = idx >> 6, i = idx & 63;
    double f = pow(10000.0, -(double)i / 64.0);
    double a = (double)pos * f;
    g_cos[idx] = (float)cos(a);
    g_sin[idx] = (float)sin(a);
}

// ---------------- tf32 helpers ----------------------------------------------
__device__ __forceinline__ float cvt_tf32(float x) {
    unsigned int r;
    asm("cvt.rna.tf32.f32 %0, %1;" : "=r"(r) : "f"(x));
    return __uint_as_float(r);
}

__device__ __forceinline__ void mma_tf32(float (&cacc)[4],
                                         const unsigned int (&a)[4],
                                         const unsigned int (&b)[2]) {
    asm volatile(
        "mma.sync.aligned.m16n8k8.row.col.f32.tf32.tf32.f32 "
        "{%0,%1,%2,%3}, {%4,%5,%6,%7}, {%8,%9}, {%0,%1,%2,%3};\n"
        : "+f"(cacc[0]), "+f"(cacc[1]), "+f"(cacc[2]), "+f"(cacc[3])
        : "r"(a[0]), "r"(a[1]), "r"(a[2]), "r"(a[3]), "r"(b[0]), "r"(b[1]));
}

// ---------------- bf16 mma helper (m16n8k16) --------------------------------
__device__ __forceinline__ void mma_bf16(float (&cacc)[4],
                                         const unsigned int (&a)[4],
                                         unsigned int b0, unsigned int b1) {
    asm volatile(
        "mma.sync.aligned.m16n8k16.row.col.f32.bf16.bf16.f32 "
        "{%0,%1,%2,%3}, {%4,%5,%6,%7}, {%8,%9}, {%0,%1,%2,%3};\n"
        : "+f"(cacc[0]), "+f"(cacc[1]), "+f"(cacc[2]), "+f"(cacc[3])
        : "r"(a[0]), "r"(a[1]), "r"(a[2]), "r"(a[3]), "r"(b0), "r"(b1));
}

// split two floats into packed bf16 hi pair + bf16 residual-lo pair
__device__ __forceinline__ void split2(float a, float b,
                                       unsigned int &hi, unsigned int &lo) {
    __nv_bfloat16 ha = __float2bfloat16(a);
    __nv_bfloat16 hb = __float2bfloat16(b);
    float ra = a - __bfloat162float(ha);
    float rb = b - __bfloat162float(hb);
    __nv_bfloat16 la = __float2bfloat16(ra);
    __nv_bfloat16 lb = __float2bfloat16(rb);
    hi = (unsigned int)__bfloat16_as_ushort(ha) |
         ((unsigned int)__bfloat16_as_ushort(hb) << 16);
    lo = (unsigned int)__bfloat16_as_ushort(la) |
         ((unsigned int)__bfloat16_as_ushort(lb) << 16);
}

// ---------------- tf32 tensor-core 128x128xK NT GEMM mainloop ---------------
__device__ __forceinline__ void gemm_tf32_mainloop(
    const float* __restrict__ Ag, const float* __restrict__ Bg,
    int K, float (&acc)[4][4][4])
{
    __shared__ float As[2][16][136];
    __shared__ float Bs[2][16][136];

    const int tid = threadIdx.x;
    const int lane = tid & 31;
    const int wid = tid >> 5;
    const int g = lane >> 2;
    const int c = lane & 3;
    const int r0 = tid >> 2;
    const int kc0 = (tid & 3) * 4;
    const int mwarp = wid >> 2;
    const int nwarp = wid & 3;
    const int KT = K >> 4;

    float4 pa0, pa1, pb0, pb1;

    pa0 = *(const float4*)(Ag + (size_t)r0 * K + kc0);
    pa1 = *(const float4*)(Ag + (size_t)(r0 + 64) * K + kc0);
    pb0 = *(const float4*)(Bg + (size_t)r0 * K + kc0);
    pb1 = *(const float4*)(Bg + (size_t)(r0 + 64) * K + kc0);
    {
        float a0[4] = {pa0.x, pa0.y, pa0.z, pa0.w};
        float a1[4] = {pa1.x, pa1.y, pa1.z, pa1.w};
        float b0[4] = {pb0.x, pb0.y, pb0.z, pb0.w};
        float b1[4] = {pb1.x, pb1.y, pb1.z, pb1.w};
        #pragma unroll
        for (int j = 0; j < 4; j++) {
            As[0][kc0 + j][r0]      = cvt_tf32(a0[j]);
            As[0][kc0 + j][r0 + 64] = cvt_tf32(a1[j]);
            Bs[0][kc0 + j][r0]      = cvt_tf32(b0[j]);
            Bs[0][kc0 + j][r0 + 64] = cvt_tf32(b1[j]);
        }
    }
    __syncthreads();

    for (int kb = 0; kb < KT; kb++) {
        const int buf = kb & 1;
        const bool has_next = (kb + 1 < KT);
        if (has_next) {
            int ko = (kb + 1) * 16 + kc0;
            pa0 = *(const float4*)(Ag + (size_t)r0 * K + ko);
            pa1 = *(const float4*)(Ag + (size_t)(r0 + 64) * K + ko);
            pb0 = *(const float4*)(Bg + (size_t)r0 * K + ko);
            pb1 = *(const float4*)(Bg + (size_t)(r0 + 64) * K + ko);
        }

        #pragma unroll
        for (int ks = 0; ks < 2; ks++) {
            const int kk = ks * 8;
            unsigned int af[4][4];
            unsigned int bf[4][2];
            #pragma unroll
            for (int mt = 0; mt < 4; mt++) {
                int m = mwarp * 64 + mt * 16 + g;
                af[mt][0] = __float_as_uint(As[buf][kk + c][m]);
                af[mt][1] = __float_as_uint(As[buf][kk + c][m + 8]);
                af[mt][2] = __float_as_uint(As[buf][kk + c + 4][m]);
                af[mt][3] = __float_as_uint(As[buf][kk + c + 4][m + 8]);
            }
            #pragma unroll
            for (int nt = 0; nt < 4; nt++) {
                int n = nwarp * 16 + (nt & 1) * 8 + (nt >> 1) * 64 + g;
                bf[nt][0] = __float_as_uint(Bs[buf][kk + c][n]);
                bf[nt][1] = __float_as_uint(Bs[buf][kk + c + 4][n]);
            }
            #pragma unroll
            for (int mt = 0; mt < 4; mt++)
                #pragma unroll
                for (int nt = 0; nt < 4; nt++)
                    mma_tf32(acc[mt][nt], af[mt], bf[nt]);
        }

        if (has_next) {
            const int nb = buf ^ 1;
            float a0[4] = {pa0.x, pa0.y, pa0.z, pa0.w};
            float a1[4] = {pa1.x, pa1.y, pa1.z, pa1.w};
            float b0[4] = {pb0.x, pb0.y, pb0.z, pb0.w};
            float b1[4] = {pb1.x, pb1.y, pb1.z, pb1.w};
            #pragma unroll
            for (int j = 0; j < 4; j++) {
                As[nb][kc0 + j][r0]      = cvt_tf32(a0[j]);
                As[nb][kc0 + j][r0 + 64] = cvt_tf32(a1[j]);
                Bs[nb][kc0 + j][r0]      = cvt_tf32(b0[j]);
                Bs[nb][kc0 + j][r0 + 64] = cvt_tf32(b1[j]);
            }
            __syncthreads();
        }
    }
}

// ---------------- QKV GEMM with fused bias + RoPE + scatter -----------------
__global__ void __launch_bounds__(256) qkv_gemm_kernel(
    const float* __restrict__ X, const float* __restrict__ W,
    const float* __restrict__ bias)
{
    float acc[4][4][4];
    #pragma unroll
    for (int i = 0; i < 4; i++)
        #pragma unroll
        for (int j = 0; j < 4; j++)
            #pragma unroll
            for (int k = 0; k < 4; k++) acc[i][j][k] = 0.f;

    const int m0 = blockIdx.y * 128;
    const int n0 = blockIdx.x * 128;
    gemm_tf32_mainloop(X + (size_t)m0 * DM, W + (size_t)n0 * DM, DM, acc);

    const int tid = threadIdx.x;
    const int lane = tid & 31;
    const int wid = tid >> 5;
    const int g = lane >> 2, c = lane & 3;
    const int mwarp = wid >> 2, nwarp = wid & 3;

    const int comp = n0 >> 11;            // 0=Q, 1=K, 2=V
    const int h = (n0 >> 7) & 15;
    float* dstQK = (comp == 0) ? g_Q : g_K;

    #pragma unroll
    for (int mt = 0; mt < 4; mt++) {
        #pragma unroll
        for (int rr = 0; rr < 2; rr++) {
            int m = m0 + mwarp * 64 + mt * 16 + g + rr * 8;
            int b = m >> 11, s = m & 2047;
            size_t base = ((size_t)(b * NH + h) * SEQ + s) * HD;
            #pragma unroll
            for (int ntp = 0; ntp < 2; ntp++) {
                #pragma unroll
                for (int e = 0; e < 2; e++) {
                    int d0 = nwarp * 16 + ntp * 8 + c * 2 + e;   // 0..63
                    float v0 = acc[mt][ntp][rr * 2 + e]     + bias[n0 + d0];
                    float v1 = acc[mt][ntp + 2][rr * 2 + e] + bias[n0 + 64 + d0];
                    if (comp == 2) {
                        g_V[base + d0]      = v0;
                        g_V[base + 64 + d0] = v1;
                    } else {
                        float co = g_cos[s * 64 + d0];
                        float sn = g_sin[s * 64 + d0];
                        dstQK[base + d0]      = v0 * co - v1 * sn;
                        dstQK[base + 64 + d0] = v1 * co + v0 * sn;
                    }
                }
            }
        }
    }
}

// ---------------- output projection GEMM (reads g_ctx) ----------------------
__global__ void __launch_bounds__(256) out_gemm_kernel(
    const float* __restrict__ W, const float* __restrict__ bias,
    float* __restrict__ C)
{
    float acc[4][4][4];
    #pragma unroll
    for (int i = 0; i < 4; i++)
        #pragma unroll
        for (int j = 0; j < 4; j++)
            #pragma unroll
            for (int k = 0; k < 4; k++) acc[i][j][k] = 0.f;

    const int m0 = blockIdx.y * 128;
    const int n0 = blockIdx.x * 128;
    gemm_tf32_mainloop(g_ctx + (size_t)m0 * DM, W + (size_t)n0 * DM, DM, acc);

    const int tid = threadIdx.x;
    const int lane = tid & 31;
    const int wid = tid >> 5;
    const int g = lane >> 2, c = lane & 3;
    const int mwarp = wid >> 2, nwarp = wid & 3;

    #pragma unroll
    for (int mt = 0; mt < 4; mt++) {
        #pragma unroll
        for (int rr = 0; rr < 2; rr++) {
            int row = m0 + mwarp * 64 + mt * 16 + g + rr * 8;
            #pragma unroll
            for (int nt = 0; nt < 4; nt++) {
                int colb = n0 + nwarp * 16 + (nt & 1) * 8 + (nt >> 1) * 64 + c * 2;
                float2 st;
                st.x = acc[mt][nt][rr * 2]     + bias[colb];
                st.y = acc[mt][nt][rr * 2 + 1] + bias[colb + 1];
                *(float2*)(C + (size_t)row * DM + colb) = st;
            }
        }
    }
}

// ---------------- tensor-core flash attention (bf16 split-3) ----------------
// BM=128 query rows per block, BN=64 keys per tile, D=128.
// 256 threads = 8 warps; warp w owns rows w*16..w*16+15 (softmax warp-local).
// All operands stored as bf16 hi + bf16 residual-lo; each mma fragment reg is
// ONE aligned LDS.32 (contiguous bf16 k-pairs). 3-mma compensation:
// Ah*Bh + Al*Bh + Ah*Bl  (error ~2^-16).
#define QSTR 136   // Q/K smem row stride (bf16 elems): bank = (4g+c) conflict-free
#define VSTR 72    // Vt/P smem row stride
#define SM_QHI 0
#define SM_QLO (SM_QHI + 128*QSTR)          // 17408
#define SM_KHI (SM_QLO + 128*QSTR)          // 34816
#define SM_KLO (SM_KHI + 64*QSTR)           // 43520
#define SM_VHI (SM_KLO + 64*QSTR)           // 52224
#define SM_VLO (SM_VHI + 128*VSTR)          // 61440
#define SM_PHI (SM_VLO + 128*VSTR)          // 70656
#define SM_PLO (SM_PHI + 128*VSTR)          // 79872
#define SM_ATTN_ELEMS (SM_PLO + 128*VSTR)   // 89088 ushorts = 178176 bytes

__global__ void __launch_bounds__(256) attn_mma_kernel() {
    extern __shared__ __align__(16) unsigned short sm[];
    unsigned short* Qhi = sm + SM_QHI;
    unsigned short* Qlo = sm + SM_QLO;
    unsigned short* Khi = sm + SM_KHI;
    unsigned short* Klo = sm + SM_KLO;
    unsigned short* Vhi = sm + SM_VHI;   // transposed: [d][s], stride VSTR
    unsigned short* Vlo = sm + SM_VLO;
    unsigned short* Phi = sm + SM_PHI;
    unsigned short* Plo = sm + SM_PLO;

    const int tid = threadIdx.x;
    const int lane = tid & 31;
    const int wid = tid >> 5;
    const int g = lane >> 2;           // 0..7
    const int c = lane & 3;            // 0..3
    const int m0 = wid * 16;
    const int qb = blockIdx.x;         // 0..15
    const int bh = blockIdx.y;         // 0..31
    const int b = bh >> 4, h = bh & 15;

    const float* Qg  = g_Q + (size_t)bh * SEQ * HD + (size_t)qb * 128 * HD;
    const float* Kg0 = g_K + (size_t)bh * SEQ * HD;
    const float* Vg0 = g_V + (size_t)bh * SEQ * HD;

    // ---- load + split Q (128x128) ----
    #pragma unroll
    for (int it = 0; it < 16; it++) {
        int idx = tid + it * 256;          // float4 index, 4096 total
        int row = idx >> 5;
        int d = (idx & 31) * 4;
        float4 v = *(const float4*)(Qg + (size_t)row * HD + d);
        unsigned int h01, l01, h23, l23;
        split2(v.x, v.y, h01, l01);
        split2(v.z, v.w, h23, l23);
        *(unsigned int*)&Qhi[row * QSTR + d]     = h01;
        *(unsigned int*)&Qhi[row * QSTR + d + 2] = h23;
        *(unsigned int*)&Qlo[row * QSTR + d]     = l01;
        *(unsigned int*)&Qlo[row * QSTR + d + 2] = l23;
    }

    float o[16][4];
    float mrow[2], lrow[2];
    #pragma unroll
    for (int i = 0; i < 16; i++)
        #pragma unroll
        for (int j = 0; j < 4; j++) o[i][j] = 0.f;
    mrow[0] = mrow[1] = -1e30f;
    lrow[0] = lrow[1] = 0.f;

    const int r0 = qb * 128 + m0 + g;   // within-sequence row of frag row 0
    const int r1 = r0 + 8;

    const int kbmax = 2 * qb + 1;
    for (int kb = 0; kb <= kbmax; kb++) {
        __syncthreads();   // protects Q (first iter) and K/Vt/P reuse
        const float* Kg = Kg0 + (size_t)kb * 64 * HD;
        const float* Vg = Vg0 + (size_t)kb * 64 * HD;

        // K tile [64][128] -> Khi/Klo (row-major)
        #pragma unroll
        for (int it = 0; it < 8; it++) {
            int idx = tid + it * 256;       // 2048 float4
            int row = idx >> 5;
            int d = (idx & 31) * 4;
            float4 v = *(const float4*)(Kg + (size_t)row * HD + d);
            unsigned int h01, l01, h23, l23;
            split2(v.x, v.y, h01, l01);
            split2(v.z, v.w, h23, l23);
            *(unsigned int*)&Khi[row * QSTR + d]     = h01;
            *(unsigned int*)&Khi[row * QSTR + d + 2] = h23;
            *(unsigned int*)&Klo[row * QSTR + d]     = l01;
            *(unsigned int*)&Klo[row * QSTR + d + 2] = l23;
        }
        // V tile [64][128] -> transposed Vt[d][s] hi/lo, s-pairs packed
        #pragma unroll
        for (int it = 0; it < 4; it++) {
            int task = tid + it * 256;      // 1024 tasks
            int s = (task >> 5) * 2;
            int d = (task & 31) * 4;
            float4 va = *(const float4*)(Vg + (size_t)s * HD + d);
            float4 vb = *(const float4*)(Vg + (size_t)(s + 1) * HD + d);
            unsigned int hi, lo;
            split2(va.x, vb.x, hi, lo);
            *(unsigned int*)&Vhi[(d + 0) * VSTR + s] = hi;
            *(unsigned int*)&Vlo[(d + 0) * VSTR + s] = lo;
            split2(va.y, vb.y, hi, lo);
            *(unsigned int*)&Vhi[(d + 1) * VSTR + s] = hi;
            *(unsigned int*)&Vlo[(d + 1) * VSTR + s] = lo;
            split2(va.z, vb.z, hi, lo);
            *(unsigned int*)&Vhi[(d + 2) * VSTR + s] = hi;
            *(unsigned int*)&Vlo[(d + 2) * VSTR + s] = lo;
            split2(va.w, vb.w, hi, lo);
            *(unsigned int*)&Vhi[(d + 3) * VSTR + s] = hi;
            *(unsigned int*)&Vlo[(d + 3) * VSTR + s] = lo;
        }
        __syncthreads();

        // ---- S = Q @ K^T (warp rows m0..m0+15, all 64 cols) ----
        float sacc[8][4];
        #pragma unroll
        for (int nt = 0; nt < 8; nt++)
            #pragma unroll
            for (int e = 0; e < 4; e++) sacc[nt][e] = 0.f;

        #pragma unroll
        for (int ks = 0; ks < 8; ks++) {
            const int k0 = ks * 16;
            unsigned int ah[4], al[4];
            ah[0] = *(unsigned int*)&Qhi[(m0 + g) * QSTR + k0 + 2 * c];
            ah[1] = *(unsigned int*)&Qhi[(m0 + g + 8) * QSTR + k0 + 2 * c];
            ah[2] = *(unsigned int*)&Qhi[(m0 + g) * QSTR + k0 + 2 * c + 8];
            ah[3] = *(unsigned int*)&Qhi[(m0 + g + 8) * QSTR + k0 + 2 * c + 8];
            al[0] = *(unsigned int*)&Qlo[(m0 + g) * QSTR + k0 + 2 * c];
            al[1] = *(unsigned int*)&Qlo[(m0 + g + 8) * QSTR + k0 + 2 * c];
            al[2] = *(unsigned int*)&Qlo[(m0 + g) * QSTR + k0 + 2 * c + 8];
            al[3] = *(unsigned int*)&Qlo[(m0 + g + 8) * QSTR + k0 + 2 * c + 8];
            #pragma unroll
            for (int nt = 0; nt < 8; nt++) {
                unsigned int bh0 = *(unsigned int*)&Khi[(nt * 8 + g) * QSTR + k0 + 2 * c];
                unsigned int bh1 = *(unsigned int*)&Khi[(nt * 8 + g) * QSTR + k0 + 2 * c + 8];
                unsigned int bl0 = *(unsigned int*)&Klo[(nt * 8 + g) * QSTR + k0 + 2 * c];
                unsigned int bl1 = *(unsigned int*)&Klo[(nt * 8 + g) * QSTR + k0 + 2 * c + 8];
                mma_bf16(sacc[nt], ah, bh0, bh1);
                mma_bf16(sacc[nt], al, bh0, bh1);
                mma_bf16(sacc[nt], ah, bl0, bl1);
            }
        }

        // ---- scale + causal mask + online softmax ----
        float smax0 = -1e30f, smax1 = -1e30f;
        #pragma unroll
        for (int nt = 0; nt < 8; nt++) {
            int col = kb * 64 + nt * 8 + 2 * c;
            float v00 = sacc[nt][0] * SCALE; if (col     > r0) v00 = -1e30f;
            float v01 = sacc[nt][1] * SCALE; if (col + 1 > r0) v01 = -1e30f;
            float v10 = sacc[nt][2] * SCALE; if (col     > r1) v10 = -1e30f;
            float v11 = sacc[nt][3] * SCALE; if (col + 1 > r1) v11 = -1e30f;
            sacc[nt][0] = v00; sacc[nt][1] = v01;
            sacc[nt][2] = v10; sacc[nt][3] = v11;
            smax0 = fmaxf(smax0, fmaxf(v00, v01));
            smax1 = fmaxf(smax1, fmaxf(v10, v11));
        }
        smax0 = fmaxf(smax0, __shfl_xor_sync(0xffffffffu, smax0, 1));
        smax0 = fmaxf(smax0, __shfl_xor_sync(0xffffffffu, smax0, 2));
        smax1 = fmaxf(smax1, __shfl_xor_sync(0xffffffffu, smax1, 1));
        smax1 = fmaxf(smax1, __shfl_xor_sync(0xffffffffu, smax1, 2));

        float mnew0 = fmaxf(mrow[0], smax0);
        float mnew1 = fmaxf(mrow[1], smax1);
        float corr0 = __expf(mrow[0] - mnew0);
        float corr1 = __expf(mrow[1] - mnew1);
        mrow[0] = mnew0; mrow[1] = mnew1;

        float rsum0 = 0.f, rsum1 = 0.f;
        #pragma unroll
        for (int nt = 0; nt < 8; nt++) {
            float p00 = __expf(sacc[nt][0] - mnew0);
            float p01 = __expf(sacc[nt][1] - mnew0);
            float p10 = __expf(sacc[nt][2] - mnew1);
            float p11 = __expf(sacc[nt][3] - mnew1);
            rsum0 += p00 + p01;
            rsum1 += p10 + p11;
            unsigned int hi, lo;
            split2(p00, p01, hi, lo);
            *(unsigned int*)&Phi[(m0 + g) * VSTR + nt * 8 + 2 * c] = hi;
            *(unsigned int*)&Plo[(m0 + g) * VSTR + nt * 8 + 2 * c] = lo;
            split2(p10, p11, hi, lo);
            *(unsigned int*)&Phi[(m0 + g + 8) * VSTR + nt * 8 + 2 * c] = hi;
            *(unsigned int*)&Plo[(m0 + g + 8) * VSTR + nt * 8 + 2 * c] = lo;
        }
        rsum0 += __shfl_xor_sync(0xffffffffu, rsum0, 1);
        rsum0 += __shfl_xor_sync(0xffffffffu, rsum0, 2);
        rsum1 += __shfl_xor_sync(0xffffffffu, rsum1, 1);
        rsum1 += __shfl_xor_sync(0xffffffffu, rsum1, 2);
        lrow[0] = lrow[0] * corr0 + rsum0;
        lrow[1] = lrow[1] * corr1 + rsum1;

        #pragma unroll
        for (int nt = 0; nt < 16; nt++) {
            o[nt][0] *= corr0; o[nt][1] *= corr0;
            o[nt][2] *= corr1; o[nt][3] *= corr1;
        }

        // ---- O += P @ V  (A = own-warp P rows, B = Vt) ----
        // (no sync needed: this warp reads only the P rows it just wrote)
        #pragma unroll
        for (int ks = 0; ks < 4; ks++) {
            const int k0 = ks * 16;
            unsigned int ah[4], al[4];
            ah[0] = *(unsigned int*)&Phi[(m0 + g) * VSTR + k0 + 2 * c];
            ah[1] = *(unsigned int*)&Phi[(m0 + g + 8) * VSTR + k0 + 2 * c];
            ah[2] = *(unsigned int*)&Phi[(m0 + g) * VSTR + k0 + 2 * c + 8];
            ah[3] = *(unsigned int*)&Phi[(m0 + g + 8) * VSTR + k0 + 2 * c + 8];
            al[0] = *(unsigned int*)&Plo[(m0 + g) * VSTR + k0 + 2 * c];
            al[1] = *(unsigned int*)&Plo[(m0 + g + 8) * VSTR + k0 + 2 * c];
            al[2] = *(unsigned int*)&Plo[(m0 + g) * VSTR + k0 + 2 * c + 8];
            al[3] = *(unsigned int*)&Plo[(m0 + g + 8) * VSTR + k0 + 2 * c + 8];
            #pragma unroll
            for (int nt = 0; nt < 16; nt++) {
                unsigned int bh0 = *(unsigned int*)&Vhi[(nt * 8 + g) * VSTR + k0 + 2 * c];
                unsigned int bh1 = *(unsigned int*)&Vhi[(nt * 8 + g) * VSTR + k0 + 2 * c + 8];
                unsigned int bl0 = *(unsigned int*)&Vlo[(nt * 8 + g) * VSTR + k0 + 2 * c];
                unsigned int bl1 = *(unsigned int*)&Vlo[(nt * 8 + g) * VSTR + k0 + 2 * c + 8];
                mma_bf16(o[nt], ah, bh0, bh1);
                mma_bf16(o[nt], al, bh0, bh1);
                mma_bf16(o[nt], ah, bl0, bl1);
            }
        }
    }

    // ---- normalize + write ctx [b*s][h*128+d] ----
    float inv0 = 1.0f / lrow[0];
    float inv1 = 1.0f / lrow[1];
    int s0 = qb * 128 + m0 + g;
    size_t base0 = ((size_t)b * SEQ + s0) * DM + h * HD;
    size_t base1 = ((size_t)b * SEQ + s0 + 8) * DM + h * HD;
    #pragma unroll
    for (int nt = 0; nt < 16; nt++) {
        int d0 = nt * 8 + 2 * c;
        float2 w0 = {o[nt][0] * inv0, o[nt][1] * inv0};
        float2 w1 = {o[nt][2] * inv1, o[nt][3] * inv1};
        *(float2*)(g_ctx + base0 + d0) = w0;
        *(float2*)(g_ctx + base1 + d0) = w1;
    }
}

// ---------------- launch ----------------------------------------------------
extern "C" void kernel_launch(void* const* d_in, const int* in_sizes, int n_in,
                              void* d_out, int out_size) {
    const float* x      = (const float*)d_in[0];
    // d_in[1] = attn_mask (causal, recomputed on the fly; unused)
    const float* Wqkv_w = (const float*)d_in[2];
    const float* Wqkv_b = (const float*)d_in[3];
    const float* out_w  = (const float*)d_in[4];
    const float* out_b  = (const float*)d_in[5];
    float* out = (float*)d_out;

    build_rope_kernel<<<(SEQ * 64 + 255) / 256, 256>>>();
    qkv_gemm_kernel<<<dim3(NQKV / 128, MROWS / 128), 256>>>(x, Wqkv_w, Wqkv_b);

    const int ATTN_SMEM = SM_ATTN_ELEMS * 2;   // 178176 bytes
    cudaFuncSetAttribute(attn_mma_kernel,
                         cudaFuncAttributeMaxDynamicSharedMemorySize, ATTN_SMEM);
    attn_mma_kernel<<<dim3(SEQ / 128, BATCH * NH), 256, ATTN_SMEM>>>();

    out_gemm_kernel<<<dim3(DM / 128, MROWS / 128), 256>>>(out_w, out_b, out);
}

// round 5
// speedup vs baseline: 2.1786x; 1.1284x over previous
#include <cuda_runtime.h>
#include <cuda_bf16.h>
#include <cstdint>
#include <stdint.h>
#include <math.h>

#define BATCH 2
#define SEQ 2048
#define NH 16
#define HD 128
#define DM 2048
#define MROWS (BATCH*SEQ)     // 4096
#define NQKV (3*DM)           // 6144
#define SCALE 0.08838834764831845f  // 1/sqrt(128)

// ---------------- scratch (static device globals: allocation-free) ----------
__device__ float g_Q[BATCH*NH*SEQ*HD];   // [b,h,s,d]
__device__ float g_K[BATCH*NH*SEQ*HD];
__device__ float g_V[BATCH*NH*SEQ*HD];
__device__ float g_ctx[MROWS*DM];        // [b*s, h*d]
__device__ float g_cos[SEQ*64];
__device__ float g_sin[SEQ*64];

// ---------------- RoPE table -------------------------------------------------
__global__ void build_rope_kernel() {
    int idx = blockIdx.x * blockDim.x + threadIdx.x;
    if (idx >= SEQ * 64) return;
    int pos = idx >> 6, i = idx & 63;
    double f = pow(10000.0, -(double)i / 64.0);
    double a = (double)pos * f;
    g_cos[idx] = (float)cos(a);
    g_sin[idx] = (float)sin(a);
}

// ---------------- tf32 helpers ----------------------------------------------
__device__ __forceinline__ float cvt_tf32(float x) {
    unsigned int r;
    asm("cvt.rna.tf32.f32 %0, %1;" : "=r"(r) : "f"(x));
    return __uint_as_float(r);
}

__device__ __forceinline__ void mma_tf32_f(float (&cacc)[4],
                                           const float4 &a, const float2 &b) {
    asm volatile(
        "mma.sync.aligned.m16n8k8.row.col.f32.tf32.tf32.f32 "
        "{%0,%1,%2,%3}, {%4,%5,%6,%7}, {%8,%9}, {%0,%1,%2,%3};\n"
        : "+f"(cacc[0]), "+f"(cacc[1]), "+f"(cacc[2]), "+f"(cacc[3])
        : "r"(__float_as_uint(a.x)), "r"(__float_as_uint(a.y)),
          "r"(__float_as_uint(a.z)), "r"(__float_as_uint(a.w)),
          "r"(__float_as_uint(b.x)), "r"(__float_as_uint(b.y)));
}

// ---------------- bf16 mma helper (m16n8k16) --------------------------------
__device__ __forceinline__ void mma_bf16(float (&cacc)[4],
                                         const unsigned int (&a)[4],
                                         unsigned int b0, unsigned int b1) {
    asm volatile(
        "mma.sync.aligned.m16n8k16.row.col.f32.bf16.bf16.f32 "
        "{%0,%1,%2,%3}, {%4,%5,%6,%7}, {%8,%9}, {%0,%1,%2,%3};\n"
        : "+f"(cacc[0]), "+f"(cacc[1]), "+f"(cacc[2]), "+f"(cacc[3])
        : "r"(a[0]), "r"(a[1]), "r"(a[2]), "r"(a[3]), "r"(b0), "r"(b1));
}

// split two floats into packed bf16 hi pair + bf16 residual-lo pair
__device__ __forceinline__ void split2(float a, float b,
                                       unsigned int &hi, unsigned int &lo) {
    __nv_bfloat16 ha = __float2bfloat16(a);
    __nv_bfloat16 hb = __float2bfloat16(b);
    float ra = a - __bfloat162float(ha);
    float rb = b - __bfloat162float(hb);
    __nv_bfloat16 la = __float2bfloat16(ra);
    __nv_bfloat16 lb = __float2bfloat16(rb);
    hi = (unsigned int)__bfloat16_as_ushort(ha) |
         ((unsigned int)__bfloat16_as_ushort(hb) << 16);
    lo = (unsigned int)__bfloat16_as_ushort(la) |
         ((unsigned int)__bfloat16_as_ushort(lb) << 16);
}

// ---------------- tf32 tensor-core 128x128xK NT GEMM mainloop ---------------
// Fragment-packed smem: each mma A operand = 1 LDS.128, B operand = 1 LDS.64.
// A blocks: [(mwarp*4+mt)*2+ks] -> 32 lanes x float4 (regs a0..a3)
// B blocks: [(nwarp*4+nt)*2+ks] -> 32 lanes x float2 (regs b0..b1)
// Single __syncthreads per 16-k tile (alternating buffers).
__device__ __forceinline__ void gemm_tf32_mainloop(
    const float* __restrict__ Ag, const float* __restrict__ Bg,
    int K, float (&acc)[4][4][4])
{
    __shared__ float4 Asf[2][16][33];   // [buf][block][lane(+pad)]
    __shared__ float2 Bsf[2][32][33];

    const int tid = threadIdx.x;
    const int lane = tid & 31;
    const int wid = tid >> 5;
    const int mwarp = wid >> 2;        // 0..1
    const int nwarp = wid & 3;         // 0..3
    const int r0 = tid >> 2;           // 0..63
    const int kc0 = (tid & 3) * 4;     // 0,4,8,12
    const int KT = K >> 4;

    // per-thread store decomposition (constant across tiles)
    const int ksS = kc0 >> 3;          // k-step of this thread's 4 k-values
    const int khS = (kc0 >> 2) & 1;    // k-half within step
    // A row r0 (mwarp'=0) and r0+64 (mwarp'=1)
    const int mtS = r0 >> 4;
    const int mrS = r0 & 15;
    const int gA = mrS & 7;
    const int mhS = mrS >> 3;
    const int regA = mhS + 2 * khS;
    // B row r0 (nh=0) and r0+64 (nh=1)
    const int nwS = r0 >> 4;
    const int nrS = r0 & 15;
    const int gB = nrS & 7;
    const int ntbS = nrS >> 3;

    float4 pa0, pa1, pb0, pb1;
    pa0 = *(const float4*)(Ag + (size_t)r0 * K + kc0);
    pa1 = *(const float4*)(Ag + (size_t)(r0 + 64) * K + kc0);
    pb0 = *(const float4*)(Bg + (size_t)r0 * K + kc0);
    pb1 = *(const float4*)(Bg + (size_t)(r0 + 64) * K + kc0);

    for (int kb = 0; kb < KT; kb++) {
        const int buf = kb & 1;
        // ---- store prefetched regs into fragment-packed smem ----
        {
            float a0[4] = {pa0.x, pa0.y, pa0.z, pa0.w};
            float a1[4] = {pa1.x, pa1.y, pa1.z, pa1.w};
            float b0[4] = {pb0.x, pb0.y, pb0.z, pb0.w};
            float b1[4] = {pb1.x, pb1.y, pb1.z, pb1.w};
            float* pA0 = (float*)&Asf[buf][ mtS * 2 + ksS     ][gA * 4] + regA;
            float* pA1 = (float*)&Asf[buf][ mtS * 2 + ksS + 8 ][gA * 4] + regA;
            float* pB0 = (float*)&Bsf[buf][(nwS * 4 + ntbS)     * 2 + ksS][gB * 4] + khS;
            float* pB1 = (float*)&Bsf[buf][(nwS * 4 + ntbS + 2) * 2 + ksS][gB * 4] + khS;
            #pragma unroll
            for (int j = 0; j < 4; j++) {
                pA0[j * 4] = cvt_tf32(a0[j]);
                pA1[j * 4] = cvt_tf32(a1[j]);
                pB0[j * 2] = cvt_tf32(b0[j]);
                pB1[j * 2] = cvt_tf32(b1[j]);
            }
        }
        __syncthreads();

        // ---- prefetch next tile ----
        if (kb + 1 < KT) {
            int ko = (kb + 1) * 16 + kc0;
            pa0 = *(const float4*)(Ag + (size_t)r0 * K + ko);
            pa1 = *(const float4*)(Ag + (size_t)(r0 + 64) * K + ko);
            pb0 = *(const float4*)(Bg + (size_t)r0 * K + ko);
            pb1 = *(const float4*)(Bg + (size_t)(r0 + 64) * K + ko);
        }

        // ---- compute: 2 k-steps x 16 mmas, wide fragment loads ----
        #pragma unroll
        for (int ks = 0; ks < 2; ks++) {
            float4 a4[4];
            float2 b2[4];
            #pragma unroll
            for (int mt = 0; mt < 4; mt++)
                a4[mt] = Asf[buf][(mwarp * 4 + mt) * 2 + ks][lane];
            #pragma unroll
            for (int nt = 0; nt < 4; nt++)
                b2[nt] = Bsf[buf][(nwarp * 4 + nt) * 2 + ks][lane];
            #pragma unroll
            for (int mt = 0; mt < 4; mt++)
                #pragma unroll
                for (int nt = 0; nt < 4; nt++)
                    mma_tf32_f(acc[mt][nt], a4[mt], b2[nt]);
        }
    }
}

// ---------------- QKV GEMM with fused bias + RoPE + scatter -----------------
__global__ void __launch_bounds__(256) qkv_gemm_kernel(
    const float* __restrict__ X, const float* __restrict__ W,
    const float* __restrict__ bias)
{
    float acc[4][4][4];
    #pragma unroll
    for (int i = 0; i < 4; i++)
        #pragma unroll
        for (int j = 0; j < 4; j++)
            #pragma unroll
            for (int k = 0; k < 4; k++) acc[i][j][k] = 0.f;

    const int m0 = blockIdx.y * 128;
    const int n0 = blockIdx.x * 128;
    gemm_tf32_mainloop(X + (size_t)m0 * DM, W + (size_t)n0 * DM, DM, acc);

    const int tid = threadIdx.x;
    const int lane = tid & 31;
    const int wid = tid >> 5;
    const int g = lane >> 2, c = lane & 3;
    const int mwarp = wid >> 2, nwarp = wid & 3;

    const int comp = n0 >> 11;            // 0=Q, 1=K, 2=V
    const int h = (n0 >> 7) & 15;
    float* dstQK = (comp == 0) ? g_Q : g_K;

    #pragma unroll
    for (int mt = 0; mt < 4; mt++) {
        #pragma unroll
        for (int rr = 0; rr < 2; rr++) {
            int m = m0 + mwarp * 64 + mt * 16 + g + rr * 8;
            int b = m >> 11, s = m & 2047;
            size_t base = ((size_t)(b * NH + h) * SEQ + s) * HD;
            #pragma unroll
            for (int ntp = 0; ntp < 2; ntp++) {
                #pragma unroll
                for (int e = 0; e < 2; e++) {
                    int d0 = nwarp * 16 + ntp * 8 + c * 2 + e;   // 0..63
                    float v0 = acc[mt][ntp][rr * 2 + e]     + bias[n0 + d0];
                    float v1 = acc[mt][ntp + 2][rr * 2 + e] + bias[n0 + 64 + d0];
                    if (comp == 2) {
                        g_V[base + d0]      = v0;
                        g_V[base + 64 + d0] = v1;
                    } else {
                        float co = g_cos[s * 64 + d0];
                        float sn = g_sin[s * 64 + d0];
                        dstQK[base + d0]      = v0 * co - v1 * sn;
                        dstQK[base + 64 + d0] = v1 * co + v0 * sn;
                    }
                }
            }
        }
    }
}

// ---------------- output projection GEMM (reads g_ctx) ----------------------
__global__ void __launch_bounds__(256) out_gemm_kernel(
    const float* __restrict__ W, const float* __restrict__ bias,
    float* __restrict__ C)
{
    float acc[4][4][4];
    #pragma unroll
    for (int i = 0; i < 4; i++)
        #pragma unroll
        for (int j = 0; j < 4; j++)
            #pragma unroll
            for (int k = 0; k < 4; k++) acc[i][j][k] = 0.f;

    const int m0 = blockIdx.y * 128;
    const int n0 = blockIdx.x * 128;
    gemm_tf32_mainloop(g_ctx + (size_t)m0 * DM, W + (size_t)n0 * DM, DM, acc);

    const int tid = threadIdx.x;
    const int lane = tid & 31;
    const int wid = tid >> 5;
    const int g = lane >> 2, c = lane & 3;
    const int mwarp = wid >> 2, nwarp = wid & 3;

    #pragma unroll
    for (int mt = 0; mt < 4; mt++) {
        #pragma unroll
        for (int rr = 0; rr < 2; rr++) {
            int row = m0 + mwarp * 64 + mt * 16 + g + rr * 8;
            #pragma unroll
            for (int nt = 0; nt < 4; nt++) {
                int colb = n0 + nwarp * 16 + (nt & 1) * 8 + (nt >> 1) * 64 + c * 2;
                float2 st;
                st.x = acc[mt][nt][rr * 2]     + bias[colb];
                st.y = acc[mt][nt][rr * 2 + 1] + bias[colb + 1];
                *(float2*)(C + (size_t)row * DM + colb) = st;
            }
        }
    }
}

// ---------------- tensor-core flash attention (bf16 split-3) ----------------
#define QSTR 136   // Q/K smem row stride (bf16 elems)
#define VSTR 72    // Vt/P smem row stride
#define SM_QHI 0
#define SM_QLO (SM_QHI + 128*QSTR)
#define SM_KHI (SM_QLO + 128*QSTR)
#define SM_KLO (SM_KHI + 64*QSTR)
#define SM_VHI (SM_KLO + 64*QSTR)
#define SM_VLO (SM_VHI + 128*VSTR)
#define SM_PHI (SM_VLO + 128*VSTR)
#define SM_PLO (SM_PHI + 128*VSTR)
#define SM_ATTN_ELEMS (SM_PLO + 128*VSTR)

__global__ void __launch_bounds__(256) attn_mma_kernel() {
    extern __shared__ __align__(16) unsigned short sm[];
    unsigned short* Qhi = sm + SM_QHI;
    unsigned short* Qlo = sm + SM_QLO;
    unsigned short* Khi = sm + SM_KHI;
    unsigned short* Klo = sm + SM_KLO;
    unsigned short* Vhi = sm + SM_VHI;   // transposed: [d][s], stride VSTR
    unsigned short* Vlo = sm + SM_VLO;
    unsigned short* Phi = sm + SM_PHI;
    unsigned short* Plo = sm + SM_PLO;

    const int tid = threadIdx.x;
    const int lane = tid & 31;
    const int wid = tid >> 5;
    const int g = lane >> 2;           // 0..7
    const int c = lane & 3;            // 0..3
    const int m0 = wid * 16;
    const int qb = blockIdx.x;         // 0..15
    const int bh = blockIdx.y;         // 0..31
    const int b = bh >> 4, h = bh & 15;

    const float* Qg  = g_Q + (size_t)bh * SEQ * HD + (size_t)qb * 128 * HD;
    const float* Kg0 = g_K + (size_t)bh * SEQ * HD;
    const float* Vg0 = g_V + (size_t)bh * SEQ * HD;

    // ---- load + split Q (128x128) ----
    #pragma unroll
    for (int it = 0; it < 16; it++) {
        int idx = tid + it * 256;
        int row = idx >> 5;
        int d = (idx & 31) * 4;
        float4 v = *(const float4*)(Qg + (size_t)row * HD + d);
        unsigned int h01, l01, h23, l23;
        split2(v.x, v.y, h01, l01);
        split2(v.z, v.w, h23, l23);
        *(unsigned int*)&Qhi[row * QSTR + d]     = h01;
        *(unsigned int*)&Qhi[row * QSTR + d + 2] = h23;
        *(unsigned int*)&Qlo[row * QSTR + d]     = l01;
        *(unsigned int*)&Qlo[row * QSTR + d + 2] = l23;
    }

    float o[16][4];
    float mrow[2], lrow[2];
    #pragma unroll
    for (int i = 0; i < 16; i++)
        #pragma unroll
        for (int j = 0; j < 4; j++) o[i][j] = 0.f;
    mrow[0] = mrow[1] = -1e30f;
    lrow[0] = lrow[1] = 0.f;

    const int r0 = qb * 128 + m0 + g;
    const int r1 = r0 + 8;

    const int kbmax = 2 * qb + 1;
    for (int kb = 0; kb <= kbmax; kb++) {
        __syncthreads();
        const float* Kg = Kg0 + (size_t)kb * 64 * HD;
        const float* Vg = Vg0 + (size_t)kb * 64 * HD;

        #pragma unroll
        for (int it = 0; it < 8; it++) {
            int idx = tid + it * 256;
            int row = idx >> 5;
            int d = (idx & 31) * 4;
            float4 v = *(const float4*)(Kg + (size_t)row * HD + d);
            unsigned int h01, l01, h23, l23;
            split2(v.x, v.y, h01, l01);
            split2(v.z, v.w, h23, l23);
            *(unsigned int*)&Khi[row * QSTR + d]     = h01;
            *(unsigned int*)&Khi[row * QSTR + d + 2] = h23;
            *(unsigned int*)&Klo[row * QSTR + d]     = l01;
            *(unsigned int*)&Klo[row * QSTR + d + 2] = l23;
        }
        #pragma unroll
        for (int it = 0; it < 4; it++) {
            int task = tid + it * 256;
            int s = (task >> 5) * 2;
            int d = (task & 31) * 4;
            float4 va = *(const float4*)(Vg + (size_t)s * HD + d);
            float4 vb = *(const float4*)(Vg + (size_t)(s + 1) * HD + d);
            unsigned int hi, lo;
            split2(va.x, vb.x, hi, lo);
            *(unsigned int*)&Vhi[(d + 0) * VSTR + s] = hi;
            *(unsigned int*)&Vlo[(d + 0) * VSTR + s] = lo;
            split2(va.y, vb.y, hi, lo);
            *(unsigned int*)&Vhi[(d + 1) * VSTR + s] = hi;
            *(unsigned int*)&Vlo[(d + 1) * VSTR + s] = lo;
            split2(va.z, vb.z, hi, lo);
            *(unsigned int*)&Vhi[(d + 2) * VSTR + s] = hi;
            *(unsigned int*)&Vlo[(d + 2) * VSTR + s] = lo;
            split2(va.w, vb.w, hi, lo);
            *(unsigned int*)&Vhi[(d + 3) * VSTR + s] = hi;
            *(unsigned int*)&Vlo[(d + 3) * VSTR + s] = lo;
        }
        __syncthreads();

        // ---- S = Q @ K^T ----
        float sacc[8][4];
        #pragma unroll
        for (int nt = 0; nt < 8; nt++)
            #pragma unroll
            for (int e = 0; e < 4; e++) sacc[nt][e] = 0.f;

        #pragma unroll
        for (int ks = 0; ks < 8; ks++) {
            const int k0 = ks * 16;
            unsigned int ah[4], al[4];
            ah[0] = *(unsigned int*)&Qhi[(m0 + g) * QSTR + k0 + 2 * c];
            ah[1] = *(unsigned int*)&Qhi[(m0 + g + 8) * QSTR + k0 + 2 * c];
            ah[2] = *(unsigned int*)&Qhi[(m0 + g) * QSTR + k0 + 2 * c + 8];
            ah[3] = *(unsigned int*)&Qhi[(m0 + g + 8) * QSTR + k0 + 2 * c + 8];
            al[0] = *(unsigned int*)&Qlo[(m0 + g) * QSTR + k0 + 2 * c];
            al[1] = *(unsigned int*)&Qlo[(m0 + g + 8) * QSTR + k0 + 2 * c];
            al[2] = *(unsigned int*)&Qlo[(m0 + g) * QSTR + k0 + 2 * c + 8];
            al[3] = *(unsigned int*)&Qlo[(m0 + g + 8) * QSTR + k0 + 2 * c + 8];
            #pragma unroll
            for (int nt = 0; nt < 8; nt++) {
                unsigned int bh0 = *(unsigned int*)&Khi[(nt * 8 + g) * QSTR + k0 + 2 * c];
                unsigned int bh1 = *(unsigned int*)&Khi[(nt * 8 + g) * QSTR + k0 + 2 * c + 8];
                unsigned int bl0 = *(unsigned int*)&Klo[(nt * 8 + g) * QSTR + k0 + 2 * c];
                unsigned int bl1 = *(unsigned int*)&Klo[(nt * 8 + g) * QSTR + k0 + 2 * c + 8];
                mma_bf16(sacc[nt], ah, bh0, bh1);
                mma_bf16(sacc[nt], al, bh0, bh1);
                mma_bf16(sacc[nt], ah, bl0, bl1);
            }
        }

        // ---- scale + causal mask + online softmax ----
        float smax0 = -1e30f, smax1 = -1e30f;
        #pragma unroll
        for (int nt = 0; nt < 8; nt++) {
            int col = kb * 64 + nt * 8 + 2 * c;
            float v00 = sacc[nt][0] * SCALE; if (col     > r0) v00 = -1e30f;
            float v01 = sacc[nt][1] * SCALE; if (col + 1 > r0) v01 = -1e30f;
            float v10 = sacc[nt][2] * SCALE; if (col     > r1) v10 = -1e30f;
            float v11 = sacc[nt][3] * SCALE; if (col + 1 > r1) v11 = -1e30f;
            sacc[nt][0] = v00; sacc[nt][1] = v01;
            sacc[nt][2] = v10; sacc[nt][3] = v11;
            smax0 = fmaxf(smax0, fmaxf(v00, v01));
            smax1 = fmaxf(smax1, fmaxf(v10, v11));
        }
        smax0 = fmaxf(smax0, __shfl_xor_sync(0xffffffffu, smax0, 1));
        smax0 = fmaxf(smax0, __shfl_xor_sync(0xffffffffu, smax0, 2));
        smax1 = fmaxf(smax1, __shfl_xor_sync(0xffffffffu, smax1, 1));
        smax1 = fmaxf(smax1, __shfl_xor_sync(0xffffffffu, smax1, 2));

        float mnew0 = fmaxf(mrow[0], smax0);
        float mnew1 = fmaxf(mrow[1], smax1);
        float corr0 = __expf(mrow[0] - mnew0);
        float corr1 = __expf(mrow[1] - mnew1);
        mrow[0] = mnew0; mrow[1] = mnew1;

        float rsum0 = 0.f, rsum1 = 0.f;
        #pragma unroll
        for (int nt = 0; nt < 8; nt++) {
            float p00 = __expf(sacc[nt][0] - mnew0);
            float p01 = __expf(sacc[nt][1] - mnew0);
            float p10 = __expf(sacc[nt][2] - mnew1);
            float p11 = __expf(sacc[nt][3] - mnew1);
            rsum0 += p00 + p01;
            rsum1 += p10 + p11;
            unsigned int hi, lo;
            split2(p00, p01, hi, lo);
            *(unsigned int*)&Phi[(m0 + g) * VSTR + nt * 8 + 2 * c] = hi;
            *(unsigned int*)&Plo[(m0 + g) * VSTR + nt * 8 + 2 * c] = lo;
            split2(p10, p11, hi, lo);
            *(unsigned int*)&Phi[(m0 + g + 8) * VSTR + nt * 8 + 2 * c] = hi;
            *(unsigned int*)&Plo[(m0 + g + 8) * VSTR + nt * 8 + 2 * c] = lo;
        }
        rsum0 += __shfl_xor_sync(0xffffffffu, rsum0, 1);
        rsum0 += __shfl_xor_sync(0xffffffffu, rsum0, 2);
        rsum1 += __shfl_xor_sync(0xffffffffu, rsum1, 1);
        rsum1 += __shfl_xor_sync(0xffffffffu, rsum1, 2);
        lrow[0] = lrow[0] * corr0 + rsum0;
        lrow[1] = lrow[1] * corr1 + rsum1;

        #pragma unroll
        for (int nt = 0; nt < 16; nt++) {
            o[nt][0] *= corr0; o[nt][1] *= corr0;
            o[nt][2] *= corr1; o[nt][3] *= corr1;
        }

        // ---- O += P @ V ----
        #pragma unroll
        for (int ks = 0; ks < 4; ks++) {
            const int k0 = ks * 16;
            unsigned int ah[4], al[4];
            ah[0] = *(unsigned int*)&Phi[(m0 + g) * VSTR + k0 + 2 * c];
            ah[1] = *(unsigned int*)&Phi[(m0 + g + 8) * VSTR + k0 + 2 * c];
            ah[2] = *(unsigned int*)&Phi[(m0 + g) * VSTR + k0 + 2 * c + 8];
            ah[3] = *(unsigned int*)&Phi[(m0 + g + 8) * VSTR + k0 + 2 * c + 8];
            al[0] = *(unsigned int*)&Plo[(m0 + g) * VSTR + k0 + 2 * c];
            al[1] = *(unsigned int*)&Plo[(m0 + g + 8) * VSTR + k0 + 2 * c];
            al[2] = *(unsigned int*)&Plo[(m0 + g) * VSTR + k0 + 2 * c + 8];
            al[3] = *(unsigned int*)&Plo[(m0 + g + 8) * VSTR + k0 + 2 * c + 8];
            #pragma unroll
            for (int nt = 0; nt < 16; nt++) {
                unsigned int bh0 = *(unsigned int*)&Vhi[(nt * 8 + g) * VSTR + k0 + 2 * c];
                unsigned int bh1 = *(unsigned int*)&Vhi[(nt * 8 + g) * VSTR + k0 + 2 * c + 8];
                unsigned int bl0 = *(unsigned int*)&Vlo[(nt * 8 + g) * VSTR + k0 + 2 * c];
                unsigned int bl1 = *(unsigned int*)&Vlo[(nt * 8 + g) * VSTR + k0 + 2 * c + 8];
                mma_bf16(o[nt], ah, bh0, bh1);
                mma_bf16(o[nt], al, bh0, bh1);
                mma_bf16(o[nt], ah, bl0, bl1);
            }
        }
    }

    // ---- normalize + write ctx ----
    float inv0 = 1.0f / lrow[0];
    float inv1 = 1.0f / lrow[1];
    int s0 = qb * 128 + m0 + g;
    size_t base0 = ((size_t)b * SEQ + s0) * DM + h * HD;
    size_t base1 = ((size_t)b * SEQ + s0 + 8) * DM + h * HD;
    #pragma unroll
    for (int nt = 0; nt < 16; nt++) {
        int d0 = nt * 8 + 2 * c;
        float2 w0 = {o[nt][0] * inv0, o[nt][1] * inv0};
        float2 w1 = {o[nt][2] * inv1, o[nt][3] * inv1};
        *(float2*)(g_ctx + base0 + d0) = w0;
        *(float2*)(g_ctx + base1 + d0) = w1;
    }
}

// ---------------- launch ----------------------------------------------------
extern "C" void kernel_launch(void* const* d_in, const int* in_sizes, int n_in,
                              void* d_out, int out_size) {
    const float* x      = (const float*)d_in[0];
    // d_in[1] = attn_mask (causal, recomputed on the fly; unused)
    const float* Wqkv_w = (const float*)d_in[2];
    const float* Wqkv_b = (const float*)d_in[3];
    const float* out_w  = (const float*)d_in[4];
    const float* out_b  = (const float*)d_in[5];
    float* out = (float*)d_out;

    build_rope_kernel<<<(SEQ * 64 + 255) / 256, 256>>>();
    qkv_gemm_kernel<<<dim3(NQKV / 128, MROWS / 128), 256>>>(x, Wqkv_w, Wqkv_b);

    const int ATTN_SMEM = SM_ATTN_ELEMS * 2;
    cudaFuncSetAttribute(attn_mma_kernel,
                         cudaFuncAttributeMaxDynamicSharedMemorySize, ATTN_SMEM);
    attn_mma_kernel<<<dim3(SEQ / 128, BATCH * NH), 256, ATTN_SMEM>>>();

    out_gemm_kernel<<<dim3(DM / 128, MROWS / 128), 256>>>(out_w, out_b, out);
}

// round 9
// speedup vs baseline: 2.2642x; 1.0393x over previous
#include <cuda_runtime.h>
#include <cuda_bf16.h>
#include <cstdint>
#include <stdint.h>
#include <math.h>

#define BATCH 2
#define SEQ 2048
#define NH 16
#define HD 128
#define DM 2048
#define MROWS (BATCH*SEQ)     // 4096
#define NQKV (3*DM)           // 6144
#define SCALE 0.08838834764831845f  // 1/sqrt(128)

// ---------------- scratch (static device globals: allocation-free) ----------
// Q/K/V stored pre-split as packed bf16 hi + residual-lo (ushort [b,h,s,d]).
__device__ unsigned short g_Qhi[BATCH*NH*SEQ*HD];
__device__ unsigned short g_Qlo[BATCH*NH*SEQ*HD];
__device__ unsigned short g_Khi[BATCH*NH*SEQ*HD];
__device__ unsigned short g_Klo[BATCH*NH*SEQ*HD];
__device__ unsigned short g_Vhi[BATCH*NH*SEQ*HD];
__device__ unsigned short g_Vlo[BATCH*NH*SEQ*HD];
__device__ float g_ctx[MROWS*DM];        // [b*s, h*d]
__device__ float g_cos[SEQ*64];
__device__ float g_sin[SEQ*64];

// ---------------- RoPE table -------------------------------------------------
__global__ void build_rope_kernel() {
    int idx = blockIdx.x * blockDim.x + threadIdx.x;
    if (idx >= SEQ * 64) return;
    int pos = idx >> 6, i = idx & 63;
    double f = pow(10000.0, -(double)i / 64.0);
    double a = (double)pos * f;
    g_cos[idx] = (float)cos(a);
    g_sin[idx] = (float)sin(a);
}

// ---------------- tf32 / bf16 helpers ---------------------------------------
__device__ __forceinline__ float cvt_tf32(float x) {
    unsigned int r;
    asm("cvt.rna.tf32.f32 %0, %1;" : "=r"(r) : "f"(x));
    return __uint_as_float(r);
}

__device__ __forceinline__ void mma_tf32_f(float (&cacc)[4],
                                           const float4 &a, const float2 &b) {
    asm volatile(
        "mma.sync.aligned.m16n8k8.row.col.f32.tf32.tf32.f32 "
        "{%0,%1,%2,%3}, {%4,%5,%6,%7}, {%8,%9}, {%0,%1,%2,%3};\n"
        : "+f"(cacc[0]), "+f"(cacc[1]), "+f"(cacc[2]), "+f"(cacc[3])
        : "r"(__float_as_uint(a.x)), "r"(__float_as_uint(a.y)),
          "r"(__float_as_uint(a.z)), "r"(__float_as_uint(a.w)),
          "r"(__float_as_uint(b.x)), "r"(__float_as_uint(b.y)));
}

__device__ __forceinline__ void mma_bf16(float (&cacc)[4],
                                         const unsigned int (&a)[4],
                                         unsigned int b0, unsigned int b1) {
    asm volatile(
        "mma.sync.aligned.m16n8k16.row.col.f32.bf16.bf16.f32 "
        "{%0,%1,%2,%3}, {%4,%5,%6,%7}, {%8,%9}, {%0,%1,%2,%3};\n"
        : "+f"(cacc[0]), "+f"(cacc[1]), "+f"(cacc[2]), "+f"(cacc[3])
        : "r"(a[0]), "r"(a[1]), "r"(a[2]), "r"(a[3]), "r"(b0), "r"(b1));
}

// split two floats into packed bf16 hi pair + bf16 residual-lo pair
__device__ __forceinline__ void split2(float a, float b,
                                       unsigned int &hi, unsigned int &lo) {
    __nv_bfloat16 ha = __float2bfloat16(a);
    __nv_bfloat16 hb = __float2bfloat16(b);
    float ra = a - __bfloat162float(ha);
    float rb = b - __bfloat162float(hb);
    __nv_bfloat16 la = __float2bfloat16(ra);
    __nv_bfloat16 lb = __float2bfloat16(rb);
    hi = (unsigned int)__bfloat16_as_ushort(ha) |
         ((unsigned int)__bfloat16_as_ushort(hb) << 16);
    lo = (unsigned int)__bfloat16_as_ushort(la) |
         ((unsigned int)__bfloat16_as_ushort(lb) << 16);
}

// ---------------- tf32 HMMA 128x256xK NT GEMM mainloop ----------------------
// 256 threads = 8 warps (2m x 4n), warp tile 64x64 (4 mt x 8 nt m16n8k8).
// Fragment-packed smem: A operand = 1 LDS.128, B operand = 1 LDS.64.
// Warp n-subtile columns (within its 128-col component half, cw = nwarp>>1):
//   col(nt) = qw*32 + (nt&1)*8 + ((nt>>1)&1)*16 + (nt>>2)*64   (qw = nwarp&1)
// so acc[.][nt] and acc[.][nt+4] are RoPE pair (d, d+64).
#define GEMM_NTHREADS 256
#define GEMM_SMEM_BYTES (2*16*33*16 + 2*64*33*8)   // Asf + Bsf = 50688

__device__ __forceinline__ void gemm_tf32_mainloop(
    const float* __restrict__ Ag, const float* __restrict__ Bg,
    int K, char* smem, float (&acc)[4][8][4])
{
    float4* Asf = (float4*)smem;                   // [2][16][33]
    float2* Bsf = (float2*)(smem + 2*16*33*16);    // [2][64][33]

    const int tid = threadIdx.x;
    const int lane = tid & 31;
    const int wid = tid >> 5;
    const int mwarp = wid >> 2;        // 0..1
    const int nwarp = wid & 3;         // 0..3
    const int r0 = tid >> 2;           // 0..63
    const int kc0 = (tid & 3) * 4;     // 0,4,8,12
    const int KT = K >> 4;

    // store decomposition (constant across tiles)
    const int ksS = kc0 >> 3;          // k-step
    const int khS = (kc0 >> 2) & 1;    // k-half within step
    // A rows r0, r0+64
    const int miS0 = r0 >> 4;          // m-subtile of row r0 (0..3)
    const int mrS = r0 & 15;
    const int gA = mrS & 7;
    const int compA = (mrS >> 3) + 2 * khS;
    // B rows r0 + 64*j, j=0..3
    int bBlk[4], gB[4];
    #pragma unroll
    for (int j = 0; j < 4; j++) {
        int nr = r0 + 64 * j;
        int cw = nr >> 7, rem = nr & 127;
        int b64 = (rem >> 6) & 1;
        int qw = (rem >> 5) & 1;
        int t16 = (rem >> 4) & 1;
        int e8 = (rem >> 3) & 1;
        gB[j] = rem & 7;
        int nw = cw * 2 + qw;
        int nt = b64 * 4 + t16 * 2 + e8;
        bBlk[j] = (nw * 8 + nt) * 2 + ksS;
    }

    float4 pa0, pa1, pb[4];
    pa0 = *(const float4*)(Ag + (size_t)r0 * K + kc0);
    pa1 = *(const float4*)(Ag + (size_t)(r0 + 64) * K + kc0);
    #pragma unroll
    for (int j = 0; j < 4; j++)
        pb[j] = *(const float4*)(Bg + (size_t)(r0 + 64 * j) * K + kc0);

    for (int kb = 0; kb < KT; kb++) {
        const int buf = kb & 1;
        // ---- store prefetched regs into fragment-packed smem ----
        {
            float a0[4] = {pa0.x, pa0.y, pa0.z, pa0.w};
            float a1[4] = {pa1.x, pa1.y, pa1.z, pa1.w};
            float* pA0 = (float*)&Asf[(buf*16 + miS0*2 + ksS)*33 + gA*4] + compA;
            float* pA1 = (float*)&Asf[(buf*16 + (miS0+4)*2 + ksS)*33 + gA*4] + compA;
            #pragma unroll
            for (int j2 = 0; j2 < 4; j2++) {
                pA0[j2 * 4] = cvt_tf32(a0[j2]);
                pA1[j2 * 4] = cvt_tf32(a1[j2]);
            }
            #pragma unroll
            for (int j = 0; j < 4; j++) {
                float b0[4] = {pb[j].x, pb[j].y, pb[j].z, pb[j].w};
                float* pB = (float*)&Bsf[(buf*64 + bBlk[j])*33 + gB[j]*4] + khS;
                #pragma unroll
                for (int j2 = 0; j2 < 4; j2++)
                    pB[j2 * 2] = cvt_tf32(b0[j2]);
            }
        }
        __syncthreads();

        // ---- prefetch next tile ----
        if (kb + 1 < KT) {
            int ko = (kb + 1) * 16 + kc0;
            pa0 = *(const float4*)(Ag + (size_t)r0 * K + ko);
            pa1 = *(const float4*)(Ag + (size_t)(r0 + 64) * K + ko);
            #pragma unroll
            for (int j = 0; j < 4; j++)
                pb[j] = *(const float4*)(Bg + (size_t)(r0 + 64 * j) * K + ko);
        }

        // ---- compute: 2 k-steps x 32 mmas, wide fragment loads ----
        #pragma unroll
        for (int ks = 0; ks < 2; ks++) {
            float4 a4[4];
            float2 b2[8];
            #pragma unroll
            for (int mt = 0; mt < 4; mt++)
                a4[mt] = Asf[(buf*16 + (mwarp*4 + mt)*2 + ks)*33 + lane];
            #pragma unroll
            for (int nt = 0; nt < 8; nt++)
                b2[nt] = Bsf[(buf*64 + (nwarp*8 + nt)*2 + ks)*33 + lane];
            #pragma unroll
            for (int mt = 0; mt < 4; mt++)
                #pragma unroll
                for (int nt = 0; nt < 8; nt++)
                    mma_tf32_f(acc[mt][nt], a4[mt], b2[nt]);
        }
    }
}

// ---------------- QKV GEMM with fused bias + RoPE + bf16-split scatter ------
__global__ void __launch_bounds__(GEMM_NTHREADS) qkv_gemm_kernel(
    const float* __restrict__ X, const float* __restrict__ W,
    const float* __restrict__ bias)
{
    extern __shared__ __align__(16) char smem[];
    float acc[4][8][4];
    #pragma unroll
    for (int i = 0; i < 4; i++)
        #pragma unroll
        for (int j = 0; j < 8; j++)
            #pragma unroll
            for (int k = 0; k < 4; k++) acc[i][j][k] = 0.f;

    const int m0 = blockIdx.y * 128;
    const int n0 = blockIdx.x * 256;
    gemm_tf32_mainloop(X + (size_t)m0 * DM, W + (size_t)n0 * DM, DM, smem, acc);

    const int tid = threadIdx.x;
    const int lane = tid & 31;
    const int wid = tid >> 5;
    const int g = lane >> 2, c = lane & 3;
    const int mwarp = wid >> 2, nwarp = wid & 3;
    const int cw = nwarp >> 1, qw = nwarp & 1;

    const int gc = n0 + cw * 128;         // global col of this warp's component
    const int comp = gc >> 11;            // 0=Q, 1=K, 2=V
    const int h = (gc >> 7) & 15;
    unsigned short* dhi = (comp == 0) ? g_Qhi : (comp == 1) ? g_Khi : g_Vhi;
    unsigned short* dlo = (comp == 0) ? g_Qlo : (comp == 1) ? g_Klo : g_Vlo;

    #pragma unroll
    for (int mt = 0; mt < 4; mt++) {
        #pragma unroll
        for (int rr = 0; rr < 2; rr++) {
            int m = m0 + mwarp * 64 + mt * 16 + g + rr * 8;
            int bb = m >> 11, s = m & 2047;
            size_t base = ((size_t)(bb * NH + h) * SEQ + s) * HD;
            #pragma unroll
            for (int nt = 0; nt < 4; nt++) {
                int d0 = qw * 32 + ((nt >> 1) & 1) * 16 + (nt & 1) * 8 + 2 * c;
                float v0e0 = acc[mt][nt][rr * 2]     + bias[gc + d0];
                float v0e1 = acc[mt][nt][rr * 2 + 1] + bias[gc + d0 + 1];
                float v1e0 = acc[mt][nt + 4][rr * 2]     + bias[gc + 64 + d0];
                float v1e1 = acc[mt][nt + 4][rr * 2 + 1] + bias[gc + 64 + d0 + 1];
                unsigned int hi, lo;
                if (comp == 2) {
                    split2(v0e0, v0e1, hi, lo);
                    *(unsigned int*)&dhi[base + d0] = hi;
                    *(unsigned int*)&dlo[base + d0] = lo;
                    split2(v1e0, v1e1, hi, lo);
                    *(unsigned int*)&dhi[base + 64 + d0] = hi;
                    *(unsigned int*)&dlo[base + 64 + d0] = lo;
                } else {
                    float2 cs = *(const float2*)&g_cos[s * 64 + d0];
                    float2 sn = *(const float2*)&g_sin[s * 64 + d0];
                    float q0e0 = v0e0 * cs.x - v1e0 * sn.x;
                    float q0e1 = v0e1 * cs.y - v1e1 * sn.y;
                    float q1e0 = v1e0 * cs.x + v0e0 * sn.x;
                    float q1e1 = v1e1 * cs.y + v0e1 * sn.y;
                    split2(q0e0, q0e1, hi, lo);
                    *(unsigned int*)&dhi[base + d0] = hi;
                    *(unsigned int*)&dlo[base + d0] = lo;
                    split2(q1e0, q1e1, hi, lo);
                    *(unsigned int*)&dhi[base + 64 + d0] = hi;
                    *(unsigned int*)&dlo[base + 64 + d0] = lo;
                }
            }
        }
    }
}

// ---------------- output projection GEMM (reads g_ctx) ----------------------
__global__ void __launch_bounds__(GEMM_NTHREADS) out_gemm_kernel(
    const float* __restrict__ W, const float* __restrict__ bias,
    float* __restrict__ C)
{
    extern __shared__ __align__(16) char smem[];
    float acc[4][8][4];
    #pragma unroll
    for (int i = 0; i < 4; i++)
        #pragma unroll
        for (int j = 0; j < 8; j++)
            #pragma unroll
            for (int k = 0; k < 4; k++) acc[i][j][k] = 0.f;

    const int m0 = blockIdx.y * 128;
    const int n0 = blockIdx.x * 256;
    gemm_tf32_mainloop(g_ctx + (size_t)m0 * DM, W + (size_t)n0 * DM, DM, smem, acc);

    const int tid = threadIdx.x;
    const int lane = tid & 31;
    const int wid = tid >> 5;
    const int g = lane >> 2, c = lane & 3;
    const int mwarp = wid >> 2, nwarp = wid & 3;
    const int cw = nwarp >> 1, qw = nwarp & 1;

    #pragma unroll
    for (int mt = 0; mt < 4; mt++) {
        #pragma unroll
        for (int rr = 0; rr < 2; rr++) {
            int row = m0 + mwarp * 64 + mt * 16 + g + rr * 8;
            #pragma unroll
            for (int nt = 0; nt < 8; nt++) {
                int colb = n0 + cw * 128 + (nt >> 2) * 64 + qw * 32 +
                           ((nt >> 1) & 1) * 16 + (nt & 1) * 8 + 2 * c;
                float2 st;
                st.x = acc[mt][nt][rr * 2]     + bias[colb];
                st.y = acc[mt][nt][rr * 2 + 1] + bias[colb + 1];
                *(float2*)(C + (size_t)row * DM + colb) = st;
            }
        }
    }
}

// ---------------- tensor-core flash attention (bf16 split-3) ----------------
// Inputs pre-split in gmem (hi/lo ushort). BM=128, BN=64, D=128.
#define QSTR 136   // Q/K smem row stride (bf16 elems)
#define VSTR 72    // Vt/P smem row stride
#define SM_QHI 0
#define SM_QLO (SM_QHI + 128*QSTR)
#define SM_KHI (SM_QLO + 128*QSTR)
#define SM_KLO (SM_KHI + 64*QSTR)
#define SM_VHI (SM_KLO + 64*QSTR)
#define SM_VLO (SM_VHI + 128*VSTR)
#define SM_PHI (SM_VLO + 128*VSTR)
#define SM_PLO (SM_PHI + 128*VSTR)
#define SM_ATTN_ELEMS (SM_PLO + 128*VSTR)

__global__ void __launch_bounds__(256) attn_mma_kernel() {
    extern __shared__ __align__(16) unsigned short sm[];
    unsigned short* Qhi = sm + SM_QHI;
    unsigned short* Qlo = sm + SM_QLO;
    unsigned short* Khi = sm + SM_KHI;
    unsigned short* Klo = sm + SM_KLO;
    unsigned short* Vhi = sm + SM_VHI;   // transposed: [d][s], stride VSTR
    unsigned short* Vlo = sm + SM_VLO;
    unsigned short* Phi = sm + SM_PHI;
    unsigned short* Plo = sm + SM_PLO;

    const int tid = threadIdx.x;
    const int lane = tid & 31;
    const int wid = tid >> 5;
    const int g = lane >> 2;           // 0..7
    const int c = lane & 3;            // 0..3
    const int m0 = wid * 16;
    const int qb = blockIdx.x;         // 0..15
    const int bh = blockIdx.y;         // 0..31
    const int b = bh >> 4, h = bh & 15;

    const size_t bhoff = (size_t)bh * SEQ * HD;
    const unsigned short* Qg_hi = g_Qhi + bhoff + (size_t)qb * 128 * HD;
    const unsigned short* Qg_lo = g_Qlo + bhoff + (size_t)qb * 128 * HD;
    const unsigned short* Kg_hi0 = g_Khi + bhoff;
    const unsigned short* Kg_lo0 = g_Klo + bhoff;
    const unsigned short* Vg_hi0 = g_Vhi + bhoff;
    const unsigned short* Vg_lo0 = g_Vlo + bhoff;

    // ---- load Q (128x128 hi+lo, straight copy) ----
    #pragma unroll
    for (int it = 0; it < 16; it++) {
        int idx = tid + it * 256;                 // 0..4095
        const unsigned short* src = (it < 8) ? Qg_hi : Qg_lo;
        unsigned short* dst = (it < 8) ? Qhi : Qlo;
        int rem = idx & 2047;
        int row = rem >> 4, d = (rem & 15) * 8;
        *(uint4*)&dst[row * QSTR + d] = *(const uint4*)&src[row * HD + d];
    }

    float o[16][4];
    float mrow[2], lrow[2];
    #pragma unroll
    for (int i = 0; i < 16; i++)
        #pragma unroll
        for (int j = 0; j < 4; j++) o[i][j] = 0.f;
    mrow[0] = mrow[1] = -1e30f;
    lrow[0] = lrow[1] = 0.f;

    const int r0 = qb * 128 + m0 + g;
    const int r1 = r0 + 8;

    const int kbmax = 2 * qb + 1;
    for (int kb = 0; kb <= kbmax; kb++) {
        __syncthreads();
        const size_t koff = (size_t)kb * 64 * HD;

        // K tile [64][128] hi+lo: straight copy
        #pragma unroll
        for (int it = 0; it < 8; it++) {
            int idx = tid + it * 256;             // 0..2047
            const unsigned short* src = (it < 4) ? Kg_hi0 : Kg_lo0;
            unsigned short* dst = (it < 4) ? Khi : Klo;
            int rem = idx & 1023;
            int row = rem >> 4, d = (rem & 15) * 8;
            *(uint4*)&dst[row * QSTR + d] = *(const uint4*)&src[koff + row * HD + d];
        }
        // V tile: transpose to [d][s-pairs] via byte_perm
        #pragma unroll
        for (int it = 0; it < 4; it++) {
            int idx = tid + it * 256;             // 0..1023
            const unsigned short* src = (it < 2) ? Vg_hi0 : Vg_lo0;
            unsigned short* dst = (it < 2) ? Vhi : Vlo;
            int rem = idx & 511;
            int s = (rem >> 4) * 2;
            int d = (rem & 15) * 8;
            uint4 ua = *(const uint4*)&src[koff + (size_t)s * HD + d];
            uint4 ub = *(const uint4*)&src[koff + (size_t)(s + 1) * HD + d];
            unsigned int uav[4] = {ua.x, ua.y, ua.z, ua.w};
            unsigned int ubv[4] = {ub.x, ub.y, ub.z, ub.w};
            #pragma unroll
            for (int j = 0; j < 4; j++) {
                unsigned int plo = __byte_perm(uav[j], ubv[j], 0x5410);
                unsigned int phi = __byte_perm(uav[j], ubv[j], 0x7632);
                *(unsigned int*)&dst[(d + 2 * j) * VSTR + s]     = plo;
                *(unsigned int*)&dst[(d + 2 * j + 1) * VSTR + s] = phi;
            }
        }
        __syncthreads();

        // ---- S = Q @ K^T ----
        float sacc[8][4];
        #pragma unroll
        for (int nt = 0; nt < 8; nt++)
            #pragma unroll
            for (int e = 0; e < 4; e++) sacc[nt][e] = 0.f;

        #pragma unroll
        for (int ks = 0; ks < 8; ks++) {
            const int k0 = ks * 16;
            unsigned int ah[4], al[4];
            ah[0] = *(unsigned int*)&Qhi[(m0 + g) * QSTR + k0 + 2 * c];
            ah[1] = *(unsigned int*)&Qhi[(m0 + g + 8) * QSTR + k0 + 2 * c];
            ah[2] = *(unsigned int*)&Qhi[(m0 + g) * QSTR + k0 + 2 * c + 8];
            ah[3] = *(unsigned int*)&Qhi[(m0 + g + 8) * QSTR + k0 + 2 * c + 8];
            al[0] = *(unsigned int*)&Qlo[(m0 + g) * QSTR + k0 + 2 * c];
            al[1] = *(unsigned int*)&Qlo[(m0 + g + 8) * QSTR + k0 + 2 * c];
            al[2] = *(unsigned int*)&Qlo[(m0 + g) * QSTR + k0 + 2 * c + 8];
            al[3] = *(unsigned int*)&Qlo[(m0 + g + 8) * QSTR + k0 + 2 * c + 8];
            #pragma unroll
            for (int nt = 0; nt < 8; nt++) {
                unsigned int bh0 = *(unsigned int*)&Khi[(nt * 8 + g) * QSTR + k0 + 2 * c];
                unsigned int bh1 = *(unsigned int*)&Khi[(nt * 8 + g) * QSTR + k0 + 2 * c + 8];
                unsigned int bl0 = *(unsigned int*)&Klo[(nt * 8 + g) * QSTR + k0 + 2 * c];
                unsigned int bl1 = *(unsigned int*)&Klo[(nt * 8 + g) * QSTR + k0 + 2 * c + 8];
                mma_bf16(sacc[nt], ah, bh0, bh1);
                mma_bf16(sacc[nt], al, bh0, bh1);
                mma_bf16(sacc[nt], ah, bl0, bl1);
            }
        }

        // ---- scale + causal mask + online softmax ----
        float smax0 = -1e30f, smax1 = -1e30f;
        #pragma unroll
        for (int nt = 0; nt < 8; nt++) {
            int col = kb * 64 + nt * 8 + 2 * c;
            float v00 = sacc[nt][0] * SCALE; if (col     > r0) v00 = -1e30f;
            float v01 = sacc[nt][1] * SCALE; if (col + 1 > r0) v01 = -1e30f;
            float v10 = sacc[nt][2] * SCALE; if (col     > r1) v10 = -1e30f;
            float v11 = sacc[nt][3] * SCALE; if (col + 1 > r1) v11 = -1e30f;
            sacc[nt][0] = v00; sacc[nt][1] = v01;
            sacc[nt][2] = v10; sacc[nt][3] = v11;
            smax0 = fmaxf(smax0, fmaxf(v00, v01));
            smax1 = fmaxf(smax1, fmaxf(v10, v11));
        }
        smax0 = fmaxf(smax0, __shfl_xor_sync(0xffffffffu, smax0, 1));
        smax0 = fmaxf(smax0, __shfl_xor_sync(0xffffffffu, smax0, 2));
        smax1 = fmaxf(smax1, __shfl_xor_sync(0xffffffffu, smax1, 1));
        smax1 = fmaxf(smax1, __shfl_xor_sync(0xffffffffu, smax1, 2));

        float mnew0 = fmaxf(mrow[0], smax0);
        float mnew1 = fmaxf(mrow[1], smax1);
        float corr0 = __expf(mrow[0] - mnew0);
        float corr1 = __expf(mrow[1] - mnew1);
        mrow[0] = mnew0; mrow[1] = mnew1;

        float rsum0 = 0.f, rsum1 = 0.f;
        #pragma unroll
        for (int nt = 0; nt < 8; nt++) {
            float p00 = __expf(sacc[nt][0] - mnew0);
            float p01 = __expf(sacc[nt][1] - mnew0);
            float p10 = __expf(sacc[nt][2] - mnew1);
            float p11 = __expf(sacc[nt][3] - mnew1);
            rsum0 += p00 + p01;
            rsum1 += p10 + p11;
            unsigned int hi, lo;
            split2(p00, p01, hi, lo);
            *(unsigned int*)&Phi[(m0 + g) * VSTR + nt * 8 + 2 * c] = hi;
            *(unsigned int*)&Plo[(m0 + g) * VSTR + nt * 8 + 2 * c] = lo;
            split2(p10, p11, hi, lo);
            *(unsigned int*)&Phi[(m0 + g + 8) * VSTR + nt * 8 + 2 * c] = hi;
            *(unsigned int*)&Plo[(m0 + g + 8) * VSTR + nt * 8 + 2 * c] = lo;
        }
        rsum0 += __shfl_xor_sync(0xffffffffu, rsum0, 1);
        rsum0 += __shfl_xor_sync(0xffffffffu, rsum0, 2);
        rsum1 += __shfl_xor_sync(0xffffffffu, rsum1, 1);
        rsum1 += __shfl_xor_sync(0xffffffffu, rsum1, 2);
        lrow[0] = lrow[0] * corr0 + rsum0;
        lrow[1] = lrow[1] * corr1 + rsum1;

        #pragma unroll
        for (int nt = 0; nt < 16; nt++) {
            o[nt][0] *= corr0; o[nt][1] *= corr0;
            o[nt][2] *= corr1; o[nt][3] *= corr1;
        }

        // ---- O += P @ V ----
        #pragma unroll
        for (int ks = 0; ks < 4; ks++) {
            const int k0 = ks * 16;
            unsigned int ah[4], al[4];
            ah[0] = *(unsigned int*)&Phi[(m0 + g) * VSTR + k0 + 2 * c];
            ah[1] = *(unsigned int*)&Phi[(m0 + g + 8) * VSTR + k0 + 2 * c];
            ah[2] = *(unsigned int*)&Phi[(m0 + g) * VSTR + k0 + 2 * c + 8];
            ah[3] = *(unsigned int*)&Phi[(m0 + g + 8) * VSTR + k0 + 2 * c + 8];
            al[0] = *(unsigned int*)&Plo[(m0 + g) * VSTR + k0 + 2 * c];
            al[1] = *(unsigned int*)&Plo[(m0 + g + 8) * VSTR + k0 + 2 * c];
            al[2] = *(unsigned int*)&Plo[(m0 + g) * VSTR + k0 + 2 * c + 8];
            al[3] = *(unsigned int*)&Plo[(m0 + g + 8) * VSTR + k0 + 2 * c + 8];
            #pragma unroll
            for (int nt = 0; nt < 16; nt++) {
                unsigned int bh0 = *(unsigned int*)&Vhi[(nt * 8 + g) * VSTR + k0 + 2 * c];
                unsigned int bh1 = *(unsigned int*)&Vhi[(nt * 8 + g) * VSTR + k0 + 2 * c + 8];
                unsigned int bl0 = *(unsigned int*)&Vlo[(nt * 8 + g) * VSTR + k0 + 2 * c];
                unsigned int bl1 = *(unsigned int*)&Vlo[(nt * 8 + g) * VSTR + k0 + 2 * c + 8];
                mma_bf16(o[nt], ah, bh0, bh1);
                mma_bf16(o[nt], al, bh0, bh1);
                mma_bf16(o[nt], ah, bl0, bl1);
            }
        }
    }

    // ---- normalize + write ctx ----
    float inv0 = 1.0f / lrow[0];
    float inv1 = 1.0f / lrow[1];
    int s0 = qb * 128 + m0 + g;
    size_t base0 = ((size_t)b * SEQ + s0) * DM + h * HD;
    size_t base1 = ((size_t)b * SEQ + s0 + 8) * DM + h * HD;
    #pragma unroll
    for (int nt = 0; nt < 16; nt++) {
        int d0 = nt * 8 + 2 * c;
        float2 w0 = {o[nt][0] * inv0, o[nt][1] * inv0};
        float2 w1 = {o[nt][2] * inv1, o[nt][3] * inv1};
        *(float2*)(g_ctx + base0 + d0) = w0;
        *(float2*)(g_ctx + base1 + d0) = w1;
    }
}

// ---------------- launch ----------------------------------------------------
extern "C" void kernel_launch(void* const* d_in, const int* in_sizes, int n_in,
                              void* d_out, int out_size) {
    const float* x      = (const float*)d_in[0];
    // d_in[1] = attn_mask (causal, recomputed on the fly; unused)
    const float* Wqkv_w = (const float*)d_in[2];
    const float* Wqkv_b = (const float*)d_in[3];
    const float* out_w  = (const float*)d_in[4];
    const float* out_b  = (const float*)d_in[5];
    float* out = (float*)d_out;

    build_rope_kernel<<<(SEQ * 64 + 255) / 256, 256>>>();

    cudaFuncSetAttribute(qkv_gemm_kernel,
                         cudaFuncAttributeMaxDynamicSharedMemorySize, GEMM_SMEM_BYTES);
    cudaFuncSetAttribute(out_gemm_kernel,
                         cudaFuncAttributeMaxDynamicSharedMemorySize, GEMM_SMEM_BYTES);

    qkv_gemm_kernel<<<dim3(NQKV / 256, MROWS / 128), GEMM_NTHREADS,
                      GEMM_SMEM_BYTES>>>(x, Wqkv_w, Wqkv_b);

    const int ATTN_SMEM = SM_ATTN_ELEMS * 2;
    cudaFuncSetAttribute(attn_mma_kernel,
                         cudaFuncAttributeMaxDynamicSharedMemorySize, ATTN_SMEM);
    attn_mma_kernel<<<dim3(SEQ / 128, BATCH * NH), 256, ATTN_SMEM>>>();

    out_gemm_kernel<<<dim3(DM / 256, MROWS / 128), GEMM_NTHREADS,
                      GEMM_SMEM_BYTES>>>(out_w, out_b, out);
}